// round 12
// baseline (speedup 1.0000x reference)
#include <cuda_runtime.h>
#include <cstdint>

#define S_LEN 2048
#define D_MODEL 2048
#define NH 16
#define HDIM 128
#define CQ_DIM 96
#define CKV_DIM 512

// ---------------- scratch (static device memory; no allocations) ----------------
__device__ float g_cq[S_LEN * CQ_DIM];
__device__ float g_ckv[S_LEN * CKV_DIM];
__device__ float g_q[S_LEN * NH * HDIM];
__device__ float g_k[S_LEN * NH * HDIM];
__device__ float g_v[S_LEN * NH * HDIM];
__device__ float g_vt[S_LEN * NH * HDIM];
__device__ float g_attn[S_LEN * NH * HDIM];
__device__ float g_qc[NH * S_LEN * 384];   // [h][s][qhi|qhi|qlo]
__device__ float g_kc[NH * S_LEN * 384];   // [h][s][khi|klo|khi]
// rounded copies of external inputs
__device__ float g_x[S_LEN * D_MODEL];
__device__ float g_wqd[CQ_DIM * D_MODEL];
__device__ float g_wqu[(NH * HDIM) * CQ_DIM];
__device__ float g_wkvd[CKV_DIM * D_MODEL];
__device__ float g_wku[(NH * HDIM) * CKV_DIM];
__device__ float g_wvu[(NH * HDIM) * CKV_DIM];
__device__ float g_wo[D_MODEL * (NH * HDIM)];

// ---------------- helpers ----------------
__device__ __forceinline__ uint32_t smem_u32(const void* p) {
    uint32_t a;
    asm("{ .reg .u64 t; cvta.to.shared.u64 t, %1; cvt.u32.u64 %0, t; }" : "=r"(a) : "l"(p));
    return a;
}
__device__ __forceinline__ float rtf32(float x) {
    uint32_t u;
    asm("cvt.rna.tf32.f32 %0, %1;" : "=r"(u) : "f"(x));
    return __uint_as_float(u);
}
__device__ __forceinline__ void split_hl(float f, float& hi, float& lo) {
    uint32_t h;
    asm("cvt.rna.tf32.f32 %0, %1;" : "=r"(h) : "f"(f));
    hi = __uint_as_float(h);
    lo = rtf32(f - hi);
}
#define CP_ASYNC(dst, src, sz) \
    asm volatile("cp.async.cg.shared.global [%0], [%1], 16, %2;" \
        :: "r"(dst), "l"(src), "r"(sz) : "memory")
#define CP_COMMIT() asm volatile("cp.async.commit_group;" ::: "memory")
#define CP_WAIT(n)  asm volatile("cp.async.wait_group %0;" :: "n"(n) : "memory")

__device__ __forceinline__ void mma_u(float* c, const uint32_t* a, const uint32_t* b) {
    asm volatile(
        "mma.sync.aligned.m16n8k8.row.col.f32.tf32.tf32.f32 "
        "{%0,%1,%2,%3}, {%4,%5,%6,%7}, {%8,%9}, {%0,%1,%2,%3};"
        : "+f"(c[0]), "+f"(c[1]), "+f"(c[2]), "+f"(c[3])
        : "r"(a[0]), "r"(a[1]), "r"(a[2]), "r"(a[3]), "r"(b[0]), "r"(b[1]));
}
__device__ __forceinline__ void ldsm_x4(uint32_t* r, uint32_t addr) {
    asm volatile("ldmatrix.sync.aligned.m8n8.x4.shared.b16 {%0,%1,%2,%3}, [%4];"
        : "=r"(r[0]), "=r"(r[1]), "=r"(r[2]), "=r"(r[3]) : "r"(addr));
}

// ---------------- tf32 mma.sync GEMM: C = A[M,K] @ B[N,K]^T (+bias) ----------------
#define LDT 36
#define TILE_FLOATS (128 * LDT)
#define STAGE_BYTES (2 * TILE_FLOATS * 4)
#define GEMM_SMEM (2 * STAGE_BYTES)

__global__ __launch_bounds__(256, 2) void gemm_mma(
    const float* __restrict__ Ab, const float* __restrict__ Bb,
    const float* __restrict__ bias, float* __restrict__ Cb,
    int N, int K, int lda, int ldb, int ldc,
    long long aBatch, long long bBatch, long long cBatch, int round_out)
{
    extern __shared__ char smem[];
    const uint32_t su = smem_u32(smem);

    const int tid = threadIdx.x;
    const int warp = tid >> 5;
    const int lane = tid & 31;
    const int wm = warp & 1;
    const int wn = warp >> 1;
    const float* A = Ab + (long long)blockIdx.z * aBatch;
    const float* B = Bb + (long long)blockIdx.z * bBatch;
    float* C = Cb + (long long)blockIdx.z * cBatch;
    const int bm0 = blockIdx.y * 128;
    const int bn0 = blockIdx.x * 128;

    int smoff[4];
    const float* aptr[4];
    const float* bptr[4];
    uint32_t bsz[4];
#pragma unroll
    for (int i = 0; i < 4; i++) {
        int idx = tid + i * 256;
        int r = idx >> 3;
        int c4 = idx & 7;
        smoff[i] = (r * LDT + c4 * 4) * 4;
        aptr[i] = A + (size_t)(bm0 + r) * lda + c4 * 4;
        bptr[i] = B + (size_t)(bn0 + r) * ldb + c4 * 4;
        bsz[i] = (bn0 + r < N) ? 16u : 0u;
    }

    const int a_off = ((wm * 64 + ((lane >> 3) & 1) * 8 + (lane & 7)) * LDT
                       + ((lane >> 4) << 2)) * 4;
    const int b_off = ((wn * 32 + ((lane >> 4) << 3) + (lane & 7)) * LDT
                       + (((lane >> 3) & 1) << 2)) * 4;

    float acc[4][4][4];
#pragma unroll
    for (int mt = 0; mt < 4; mt++)
#pragma unroll
        for (int nt = 0; nt < 4; nt++)
#pragma unroll
            for (int j = 0; j < 4; j++) acc[mt][nt][j] = 0.f;

    const int nsteps = K >> 5;
    {
        uint32_t sb = su;
#pragma unroll
        for (int i = 0; i < 4; i++) CP_ASYNC(sb + smoff[i], aptr[i], 16u);
#pragma unroll
        for (int i = 0; i < 4; i++) CP_ASYNC(sb + TILE_FLOATS * 4 + smoff[i], bptr[i], bsz[i]);
        CP_COMMIT();
    }

    for (int s = 0; s < nsteps; s++) {
        if (s + 1 < nsteps) {
            uint32_t sb = su + ((s + 1) & 1) * STAGE_BYTES;
            const int k0 = (s + 1) << 5;
#pragma unroll
            for (int i = 0; i < 4; i++) CP_ASYNC(sb + smoff[i], aptr[i] + k0, 16u);
#pragma unroll
            for (int i = 0; i < 4; i++) CP_ASYNC(sb + TILE_FLOATS * 4 + smoff[i], bptr[i] + k0, bsz[i]);
            CP_COMMIT();
            CP_WAIT(1);
        } else {
            CP_WAIT(0);
        }
        __syncthreads();

        const uint32_t sa = su + (s & 1) * STAGE_BYTES + a_off;
        const uint32_t sbb = su + (s & 1) * STAGE_BYTES + TILE_FLOATS * 4 + b_off;

#pragma unroll
        for (int kk = 0; kk < 4; kk++) {
            uint32_t a_regs[4][4], b_regs[2][4];
#pragma unroll
            for (int mt = 0; mt < 4; mt++)
                ldsm_x4(a_regs[mt], sa + (mt * 16 * LDT + kk * 8) * 4);
#pragma unroll
            for (int pr = 0; pr < 2; pr++)
                ldsm_x4(b_regs[pr], sbb + (pr * 16 * LDT + kk * 8) * 4);
#pragma unroll
            for (int mt = 0; mt < 4; mt++)
#pragma unroll
                for (int nt = 0; nt < 4; nt++)
                    mma_u(acc[mt][nt], a_regs[mt], &b_regs[nt >> 1][(nt & 1) * 2]);
        }
        __syncthreads();   // buffer-reuse safety before next step's cp.async issue
    }

    const bool has_bias = (bias != nullptr);
    const int gr = lane >> 2;
    const int gc = lane & 3;
#pragma unroll
    for (int mt = 0; mt < 4; mt++) {
        int r0 = bm0 + wm * 64 + mt * 16 + gr;
#pragma unroll
        for (int nt = 0; nt < 4; nt++) {
            int c0 = bn0 + wn * 32 + nt * 8 + gc * 2;
            if (c0 < N) {
                float bx = has_bias ? bias[c0] : 0.f;
                float by = has_bias ? bias[c0 + 1] : 0.f;
                float v00 = acc[mt][nt][0] + bx, v01 = acc[mt][nt][1] + by;
                float v10 = acc[mt][nt][2] + bx, v11 = acc[mt][nt][3] + by;
                if (round_out) {
                    v00 = rtf32(v00); v01 = rtf32(v01);
                    v10 = rtf32(v10); v11 = rtf32(v11);
                }
                *(float2*)&C[(size_t)r0 * ldc + c0] = make_float2(v00, v01);
                *(float2*)&C[(size_t)(r0 + 8) * ldc + c0] = make_float2(v10, v11);
            }
        }
    }
}

// ---------------- one-shot rounding of all external operands ----------------
__device__ __forceinline__ void round_seg(const float* s, float* d, int n4,
                                          int gid, int gsz) {
    for (int i = gid; i < n4; i += gsz) {
        float4 v = ((const float4*)s)[i];
        v.x = rtf32(v.x); v.y = rtf32(v.y); v.z = rtf32(v.z); v.w = rtf32(v.w);
        ((float4*)d)[i] = v;
    }
}
__global__ __launch_bounds__(256) void round_all(
    const float* x, float* rx, const float* wqd, float* rwqd,
    const float* wqu, float* rwqu, const float* wkvd, float* rwkvd,
    const float* wku, float* rwku, const float* wvu, float* rwvu,
    const float* wo, float* rwo)
{
    int gid = blockIdx.x * blockDim.x + threadIdx.x;
    int gsz = gridDim.x * blockDim.x;
    round_seg(x, rx, S_LEN * D_MODEL / 4, gid, gsz);
    round_seg(wqd, rwqd, CQ_DIM * D_MODEL / 4, gid, gsz);
    round_seg(wqu, rwqu, NH * HDIM * CQ_DIM / 4, gid, gsz);
    round_seg(wkvd, rwkvd, CKV_DIM * D_MODEL / 4, gid, gsz);
    round_seg(wku, rwku, NH * HDIM * CKV_DIM / 4, gid, gsz);
    round_seg(wvu, rwvu, NH * HDIM * CKV_DIM / 4, gid, gsz);
    round_seg(wo, rwo, D_MODEL * NH * HDIM / 4, gid, gsz);
}

// ---------------- RoPE + hi/lo pack (K=384 concat) ----------------
__global__ __launch_bounds__(256) void rope_pack(
    const float* __restrict__ q, const float* __restrict__ k,
    const float* __restrict__ cosb, const float* __restrict__ sinb,
    float* __restrict__ qc, float* __restrict__ kc)
{
    int idx = blockIdx.x * blockDim.x + threadIdx.x;
    int dh = idx & 63;
    int t = idx >> 6;
    int h = t & (NH - 1);
    int s = t >> 4;
    if (s >= S_LEN) return;

    float c1 = cosb[s * HDIM + dh];
    float s1 = sinb[s * HDIM + dh];
    float c2 = cosb[s * HDIM + dh + 64];
    float s2 = sinb[s * HDIM + dh + 64];

    size_t base = (size_t)s * (NH * HDIM) + h * HDIM + dh;
    const float sc = 0.08838834764831845f;  // 1/sqrt(128)

    float q1 = q[base], q2 = q[base + 64];
    float qa = (q1 * c1 - q2 * s1) * sc;
    float qb = (q2 * c2 + q1 * s2) * sc;
    float k1 = k[base], k2 = k[base + 64];
    float ka = k1 * c1 - k2 * s1;
    float kb = k2 * c2 + k1 * s2;

    float qah, qal, qbh, qbl, kah, kal, kbh, kbl;
    split_hl(qa, qah, qal); split_hl(qb, qbh, qbl);
    split_hl(ka, kah, kal); split_hl(kb, kbh, kbl);

    size_t ob = ((size_t)h * S_LEN + s) * 384 + dh;
    qc[ob]       = qah; qc[ob + 64]       = qbh;
    qc[ob + 128] = qah; qc[ob + 128 + 64] = qbh;
    qc[ob + 256] = qal; qc[ob + 256 + 64] = qbl;
    kc[ob]       = kah; kc[ob + 64]       = kbh;
    kc[ob + 128] = kal; kc[ob + 128 + 64] = kbl;
    kc[ob + 256] = kah; kc[ob + 256 + 64] = kbh;
}

// ---------------- 2048x2048 transpose (v -> v^T), rounds output ----------------
__global__ void transpose2048(const float* __restrict__ src, float* __restrict__ dst)
{
    __shared__ float t[32][33];
    int x = threadIdx.x, y = threadIdx.y;
    int r0 = blockIdx.y * 32, c0 = blockIdx.x * 32;
#pragma unroll
    for (int i = 0; i < 32; i += 8)
        t[y + i][x] = src[(size_t)(r0 + y + i) * 2048 + c0 + x];
    __syncthreads();
#pragma unroll
    for (int i = 0; i < 32; i += 8)
        dst[(size_t)(c0 + y + i) * 2048 + r0 + x] = rtf32(t[x][y + i]);
}

// ---------------- flash attention (mma.sync tf32, K=384 concat QK) ----------------
// Br=64 q rows per CTA, Bc=128 kv per block, 16 blocks. 256 threads.
#define LDQP 388
#define QP_BYTES (64 * LDQP * 4)                 // 99328
#define FB_OFF QP_BYTES
#define FB_BYTES (128 * LDT * 4)                 // 18432
#define P_OFF (FB_OFF + 2 * FB_BYTES)            // 136192
#define LDP 132
#define P_BYTES (64 * LDP * 4)                   // 33792
#define RED_OFF (P_OFF + P_BYTES)                // 169984
#define FLASH_SMEM (RED_OFF + 2048)              // 172032

__global__ __launch_bounds__(256, 1) void flash_mma(
    const float* __restrict__ qc, const float* __restrict__ kc,
    const float* __restrict__ vt, float* __restrict__ attn)
{
    extern __shared__ char smem[];
    const uint32_t su = smem_u32(smem);
    float* Ps = (float*)(smem + P_OFF);
    float* redM = (float*)(smem + RED_OFF);
    float* redS = redM + 256;

    const int tid = threadIdx.x;
    const int warp = tid >> 5;
    const int lane = tid & 31;
    const int wm = warp & 1;
    const int wn = warp >> 1;
    const int gr = lane >> 2;
    const int gc = lane & 3;
    const int h = blockIdx.y;
    const int q0 = blockIdx.x * 64;

    const float* Qg = qc + ((size_t)h * S_LEN + q0) * 384;
    const float* Kg = kc + (size_t)h * S_LEN * 384;
    const float* Vg = vt + (size_t)h * HDIM * 2048;   // [d][s]

    const int aq_off = ((wm * 32 + ((lane >> 3) & 1) * 8 + (lane & 7)) * LDQP
                        + ((lane >> 4) << 2)) * 4;
    const int ap_off = ((wm * 32 + ((lane >> 3) & 1) * 8 + (lane & 7)) * LDP
                        + ((lane >> 4) << 2)) * 4;
    const int b_off = ((wn * 32 + ((lane >> 4) << 3) + (lane & 7)) * LDT
                       + (((lane >> 3) & 1) << 2)) * 4;

    // Q' tile load: 64 rows x 384 floats = 6144 float4, 24 per thread (FIXED)
#pragma unroll
    for (int i = 0; i < 24; i++) {
        int idx = tid + i * 256;
        int r = idx / 96;
        int c4 = idx % 96;
        CP_ASYNC(su + (r * LDQP + c4 * 4) * 4, Qg + (size_t)r * 384 + c4 * 4, 16u);
    }
    CP_COMMIT();

    auto load_chunk = [&](int bufsel, const float* src, int ld) {
#pragma unroll
        for (int i = 0; i < 4; i++) {
            int idx = tid + i * 256;
            int r = idx >> 3;
            int c4 = idx & 7;
            CP_ASYNC(su + FB_OFF + bufsel * FB_BYTES + (r * LDT + c4 * 4) * 4,
                     src + (size_t)r * ld + c4 * 4, 16u);
        }
    };

    // prologue: K chunk 0 of block 0
    load_chunk(0, Kg, 384);
    CP_COMMIT();

    float accO[2][4][4];
    float m_i[4], l_i[4];
#pragma unroll
    for (int mt = 0; mt < 2; mt++)
#pragma unroll
        for (int nt = 0; nt < 4; nt++)
#pragma unroll
            for (int j = 0; j < 4; j++) accO[mt][nt][j] = 0.f;
#pragma unroll
    for (int s = 0; s < 4; s++) { m_i[s] = -1e30f; l_i[s] = 0.f; }

    for (int b = 0; b < 16; b++) {
        const int kv0 = b * 128;
        float accS[2][4][4];
#pragma unroll
        for (int mt = 0; mt < 2; mt++)
#pragma unroll
            for (int nt = 0; nt < 4; nt++)
#pragma unroll
                for (int j = 0; j < 4; j++) accS[mt][nt][j] = 0.f;

        // ---- QK^T: 12 chunks of K=32 over the 384-wide concat ----
        for (int c = 0; c < 12; c++) {
            if (c < 11)
                load_chunk((c + 1) & 1, Kg + (size_t)kv0 * 384 + (c + 1) * 32, 384);
            else
                load_chunk(0, Vg + kv0, 2048);   // V chunk 0
            CP_COMMIT();
            CP_WAIT(1);
            __syncthreads();

            const uint32_t sq = su + aq_off + (c * 32) * 4;
            const uint32_t sb = su + FB_OFF + (c & 1) * FB_BYTES + b_off;
#pragma unroll
            for (int kk = 0; kk < 4; kk++) {
                uint32_t a_regs[2][4], b_regs[2][4];
#pragma unroll
                for (int mt = 0; mt < 2; mt++)
                    ldsm_x4(a_regs[mt], sq + (mt * 16 * LDQP + kk * 8) * 4);
#pragma unroll
                for (int pr = 0; pr < 2; pr++)
                    ldsm_x4(b_regs[pr], sb + (pr * 16 * LDT + kk * 8) * 4);
#pragma unroll
                for (int mt = 0; mt < 2; mt++)
#pragma unroll
                    for (int nt = 0; nt < 4; nt++)
                        mma_u(accS[mt][nt], a_regs[mt], &b_regs[nt >> 1][(nt & 1) * 2]);
            }
            __syncthreads();
        }

        // ---- online softmax ----
        int rown[4];
        float pm[4];
#pragma unroll
        for (int mt = 0; mt < 2; mt++)
#pragma unroll
            for (int hh = 0; hh < 2; hh++) {
                int sl = mt * 2 + hh;
                rown[sl] = wm * 32 + mt * 16 + hh * 8 + gr;
                float v = accS[mt][0][hh * 2];
#pragma unroll
                for (int nt = 0; nt < 4; nt++) {
                    v = fmaxf(v, accS[mt][nt][hh * 2]);
                    v = fmaxf(v, accS[mt][nt][hh * 2 + 1]);
                }
                pm[sl] = v;
            }
#pragma unroll
        for (int sl = 0; sl < 4; sl++) {
            pm[sl] = fmaxf(pm[sl], __shfl_xor_sync(~0u, pm[sl], 1));
            pm[sl] = fmaxf(pm[sl], __shfl_xor_sync(~0u, pm[sl], 2));
        }
        if (gc == 0)
#pragma unroll
            for (int sl = 0; sl < 4; sl++) redM[rown[sl] * 4 + wn] = pm[sl];
        __syncthreads();

        float sc[4];
#pragma unroll
        for (int sl = 0; sl < 4; sl++) {
            float mb = fmaxf(fmaxf(redM[rown[sl] * 4 + 0], redM[rown[sl] * 4 + 1]),
                             fmaxf(redM[rown[sl] * 4 + 2], redM[rown[sl] * 4 + 3]));
            float mnew = fmaxf(m_i[sl], mb);
            sc[sl] = __expf(m_i[sl] - mnew);
            m_i[sl] = mnew;
        }

        float ps[4] = {0.f, 0.f, 0.f, 0.f};
#pragma unroll
        for (int mt = 0; mt < 2; mt++)
#pragma unroll
            for (int nt = 0; nt < 4; nt++)
#pragma unroll
                for (int j = 0; j < 4; j++) {
                    int sl = mt * 2 + (j >> 1);
                    float e = rtf32(__expf(accS[mt][nt][j] - m_i[sl]));
                    accS[mt][nt][j] = e;
                    ps[sl] += e;
                    accO[mt][nt][j] *= sc[sl];
                }
#pragma unroll
        for (int sl = 0; sl < 4; sl++) {
            ps[sl] += __shfl_xor_sync(~0u, ps[sl], 1);
            ps[sl] += __shfl_xor_sync(~0u, ps[sl], 2);
        }
        if (gc == 0)
#pragma unroll
            for (int sl = 0; sl < 4; sl++) redS[rown[sl] * 4 + wn] = ps[sl];

        // stage P to smem
#pragma unroll
        for (int mt = 0; mt < 2; mt++) {
            int r0 = wm * 32 + mt * 16 + gr;
#pragma unroll
            for (int nt = 0; nt < 4; nt++) {
                int c0 = wn * 32 + nt * 8 + gc * 2;
                *(float2*)&Ps[r0 * LDP + c0] = make_float2(accS[mt][nt][0], accS[mt][nt][1]);
                *(float2*)&Ps[(r0 + 8) * LDP + c0] = make_float2(accS[mt][nt][2], accS[mt][nt][3]);
            }
        }
        __syncthreads();

#pragma unroll
        for (int sl = 0; sl < 4; sl++) {
            float s4 = redS[rown[sl] * 4 + 0] + redS[rown[sl] * 4 + 1]
                     + redS[rown[sl] * 4 + 2] + redS[rown[sl] * 4 + 3];
            l_i[sl] = l_i[sl] * sc[sl] + s4;
        }

        // ---- O += P @ V : 4 chunks of K=32 over Bc=128 ----
        for (int c = 0; c < 4; c++) {
            if (c < 3)
                load_chunk((c + 1) & 1, Vg + kv0 + (c + 1) * 32, 2048);
            else if (b < 15)
                load_chunk(0, Kg + (size_t)(kv0 + 128) * 384, 384);
            CP_COMMIT();
            CP_WAIT(1);
            __syncthreads();

            const uint32_t sp = su + P_OFF + ap_off + (c * 32) * 4;
            const uint32_t sb = su + FB_OFF + (c & 1) * FB_BYTES + b_off;
#pragma unroll
            for (int kk = 0; kk < 4; kk++) {
                uint32_t a_regs[2][4], b_regs[2][4];
#pragma unroll
                for (int mt = 0; mt < 2; mt++)
                    ldsm_x4(a_regs[mt], sp + (mt * 16 * LDP + kk * 8) * 4);
#pragma unroll
                for (int pr = 0; pr < 2; pr++)
                    ldsm_x4(b_regs[pr], sb + (pr * 16 * LDT + kk * 8) * 4);
#pragma unroll
                for (int mt = 0; mt < 2; mt++)
#pragma unroll
                    for (int nt = 0; nt < 4; nt++)
                        mma_u(accO[mt][nt], a_regs[mt], &b_regs[nt >> 1][(nt & 1) * 2]);
            }
            __syncthreads();
        }
    }

    // epilogue
    float inv[4];
#pragma unroll
    for (int sl = 0; sl < 4; sl++) inv[sl] = 1.f / l_i[sl];
#pragma unroll
    for (int mt = 0; mt < 2; mt++) {
        int r0 = q0 + wm * 32 + mt * 16 + gr;
#pragma unroll
        for (int nt = 0; nt < 4; nt++) {
            int c0 = h * HDIM + wn * 32 + nt * 8 + gc * 2;
            *(float2*)&attn[(size_t)r0 * 2048 + c0] =
                make_float2(accO[mt][nt][0] * inv[mt * 2], accO[mt][nt][1] * inv[mt * 2]);
            *(float2*)&attn[(size_t)(r0 + 8) * 2048 + c0] =
                make_float2(accO[mt][nt][2] * inv[mt * 2 + 1], accO[mt][nt][3] * inv[mt * 2 + 1]);
        }
    }
}

// ---------------- launch ----------------
extern "C" void kernel_launch(void* const* d_in, const int* in_sizes, int n_in,
                              void* d_out, int out_size)
{
    const float* x        = (const float*)d_in[0];
    const float* rope_cos = (const float*)d_in[1];
    const float* rope_sin = (const float*)d_in[2];
    const float* wq_down  = (const float*)d_in[3];
    const float* bq_down  = (const float*)d_in[4];
    const float* wq_up    = (const float*)d_in[5];
    const float* bq_up    = (const float*)d_in[6];
    const float* wkv_down = (const float*)d_in[7];
    const float* bkv_down = (const float*)d_in[8];
    const float* wk_up    = (const float*)d_in[9];
    const float* bk_up    = (const float*)d_in[10];
    const float* wv_up    = (const float*)d_in[11];
    const float* bv_up    = (const float*)d_in[12];
    const float* wo       = (const float*)d_in[13];
    const float* bo       = (const float*)d_in[14];
    float* out = (float*)d_out;

    float *cq, *ckv, *q, *k, *v, *vt, *attn, *qc, *kc;
    float *rx, *rwqd, *rwqu, *rwkvd, *rwku, *rwvu, *rwo;
    cudaGetSymbolAddress((void**)&cq,     g_cq);
    cudaGetSymbolAddress((void**)&ckv,    g_ckv);
    cudaGetSymbolAddress((void**)&q,      g_q);
    cudaGetSymbolAddress((void**)&k,      g_k);
    cudaGetSymbolAddress((void**)&v,      g_v);
    cudaGetSymbolAddress((void**)&vt,     g_vt);
    cudaGetSymbolAddress((void**)&attn,   g_attn);
    cudaGetSymbolAddress((void**)&qc,     g_qc);
    cudaGetSymbolAddress((void**)&kc,     g_kc);
    cudaGetSymbolAddress((void**)&rx,     g_x);
    cudaGetSymbolAddress((void**)&rwqd,   g_wqd);
    cudaGetSymbolAddress((void**)&rwqu,   g_wqu);
    cudaGetSymbolAddress((void**)&rwkvd,  g_wkvd);
    cudaGetSymbolAddress((void**)&rwku,   g_wku);
    cudaGetSymbolAddress((void**)&rwvu,   g_wvu);
    cudaGetSymbolAddress((void**)&rwo,    g_wo);

    cudaFuncSetAttribute(gemm_mma, cudaFuncAttributeMaxDynamicSharedMemorySize, GEMM_SMEM);
    cudaFuncSetAttribute(flash_mma, cudaFuncAttributeMaxDynamicSharedMemorySize, FLASH_SMEM);

    // 0: round all external operands
    round_all<<<512, 256>>>(x, rx, wq_down, rwqd, wq_up, rwqu, wkv_down, rwkvd,
                            wk_up, rwku, wv_up, rwvu, wo, rwo);

    // 1..5: projections
    gemm_mma<<<dim3(1, 16, 1), 256, GEMM_SMEM>>>(
        rx, rwqd, bq_down, cq, CQ_DIM, D_MODEL, D_MODEL, D_MODEL, CQ_DIM, 0, 0, 0, 1);
    gemm_mma<<<dim3(16, 16, 1), 256, GEMM_SMEM>>>(
        cq, rwqu, bq_up, q, 2048, CQ_DIM, CQ_DIM, CQ_DIM, 2048, 0, 0, 0, 0);
    gemm_mma<<<dim3(4, 16, 1), 256, GEMM_SMEM>>>(
        rx, rwkvd, bkv_down, ckv, CKV_DIM, D_MODEL, D_MODEL, D_MODEL, CKV_DIM, 0, 0, 0, 1);
    gemm_mma<<<dim3(16, 16, 1), 256, GEMM_SMEM>>>(
        ckv, rwku, bk_up, k, 2048, CKV_DIM, CKV_DIM, CKV_DIM, 2048, 0, 0, 0, 0);
    gemm_mma<<<dim3(16, 16, 1), 256, GEMM_SMEM>>>(          // launch #5 -> ncu profile
        ckv, rwvu, bv_up, v, 2048, CKV_DIM, CKV_DIM, CKV_DIM, 2048, 0, 0, 0, 0);

    // 6: rope + hi/lo pack ; 7: v^T
    rope_pack<<<(S_LEN * NH * 64) / 256, 256>>>(q, k, rope_cos, rope_sin, qc, kc);
    transpose2048<<<dim3(64, 64), dim3(32, 8)>>>(v, vt);

    // 8: flash attention
    flash_mma<<<dim3(S_LEN / 64, NH), 256, FLASH_SMEM>>>(qc, kc, vt, attn);

    // 9: out = attn @ wo^T + bo
    gemm_mma<<<dim3(16, 16, 1), 256, GEMM_SMEM>>>(
        attn, rwo, bo, out, 2048, 2048, 2048, 2048, 2048, 0, 0, 0, 0);
}

// round 13
// speedup vs baseline: 1.4225x; 1.4225x over previous
#include <cuda_runtime.h>
#include <cstdint>

#define S_LEN 2048
#define D_MODEL 2048
#define NH 16
#define HDIM 128
#define CQ_DIM 96
#define CKV_DIM 512
#define NDOWN 608                 // 96 + 512
#define NUV 4096                  // 2048 + 2048

// ---------------- scratch (static device memory; no allocations) ----------------
__device__ float g_cqkv[S_LEN * NDOWN];                   // [s][cq|ckv]
__device__ float g_q[S_LEN * NH * HDIM];
__device__ float g_kv[S_LEN * NUV];                       // [s][k(2048)|v(2048)]
__device__ float g_vt[S_LEN * NH * HDIM];
__device__ float g_attn[S_LEN * NH * HDIM];
__device__ float g_qc[NH * S_LEN * 384];                  // [h][s][qhi|qhi|qlo]
__device__ float g_kc[NH * S_LEN * 384];                  // [h][s][khi|klo|khi]
__device__ float g_logits[(long long)NH * S_LEN * S_LEN]; // 256 MB
// rounded/merged copies of external inputs
__device__ float g_x[S_LEN * D_MODEL];
__device__ float g_wd[NDOWN * D_MODEL];                   // [wq_down; wkv_down]
__device__ float g_bd[NDOWN];
__device__ float g_wqu[(NH * HDIM) * CQ_DIM];
__device__ float g_wuv[NUV * CKV_DIM];                    // [wk_up; wv_up]
__device__ float g_buv[NUV];
__device__ float g_wo[D_MODEL * (NH * HDIM)];

// ---------------- helpers ----------------
__device__ __forceinline__ uint32_t smem_u32(const void* p) {
    uint32_t a;
    asm("{ .reg .u64 t; cvta.to.shared.u64 t, %1; cvt.u32.u64 %0, t; }" : "=r"(a) : "l"(p));
    return a;
}
__device__ __forceinline__ float rtf32(float x) {
    uint32_t u;
    asm("cvt.rna.tf32.f32 %0, %1;" : "=r"(u) : "f"(x));
    return __uint_as_float(u);
}
__device__ __forceinline__ void split_hl(float f, float& hi, float& lo) {
    uint32_t h;
    asm("cvt.rna.tf32.f32 %0, %1;" : "=r"(h) : "f"(f));
    hi = __uint_as_float(h);
    lo = rtf32(f - hi);
}
#define CP_ASYNC(dst, src, sz) \
    asm volatile("cp.async.cg.shared.global [%0], [%1], 16, %2;" \
        :: "r"(dst), "l"(src), "r"(sz) : "memory")
#define CP_COMMIT() asm volatile("cp.async.commit_group;" ::: "memory")
#define CP_WAIT(n)  asm volatile("cp.async.wait_group %0;" :: "n"(n) : "memory")

__device__ __forceinline__ void mma_u(float* c, const uint32_t* a, const uint32_t* b) {
    asm volatile(
        "mma.sync.aligned.m16n8k8.row.col.f32.tf32.tf32.f32 "
        "{%0,%1,%2,%3}, {%4,%5,%6,%7}, {%8,%9}, {%0,%1,%2,%3};"
        : "+f"(c[0]), "+f"(c[1]), "+f"(c[2]), "+f"(c[3])
        : "r"(a[0]), "r"(a[1]), "r"(a[2]), "r"(a[3]), "r"(b[0]), "r"(b[1]));
}
__device__ __forceinline__ void ldsm_x4(uint32_t* r, uint32_t addr) {
    asm volatile("ldmatrix.sync.aligned.m8n8.x4.shared.b16 {%0,%1,%2,%3}, [%4];"
        : "=r"(r[0]), "=r"(r[1]), "=r"(r[2]), "=r"(r[3]) : "r"(addr));
}

// ---------------- tf32 mma.sync GEMM: C = A[M,K] @ B[N,K]^T (+bias) ----------------
// BM=128, BN=128, BK=32, 256 threads, single-barrier cp.async pipeline.
#define LDT 36
#define TILE_FLOATS (128 * LDT)
#define STAGE_BYTES (2 * TILE_FLOATS * 4)
#define GEMM_SMEM (2 * STAGE_BYTES)

__global__ __launch_bounds__(256, 2) void gemm_mma(
    const float* __restrict__ Ab, const float* __restrict__ Bb,
    const float* __restrict__ bias, float* __restrict__ Cb,
    int N, int K, int lda, int ldb, int ldc,
    long long aBatch, long long bBatch, long long cBatch, int round_out)
{
    extern __shared__ char smem[];
    const uint32_t su = smem_u32(smem);

    const int tid = threadIdx.x;
    const int warp = tid >> 5;
    const int lane = tid & 31;
    const int wm = warp & 1;
    const int wn = warp >> 1;
    const float* A = Ab + (long long)blockIdx.z * aBatch;
    const float* B = Bb + (long long)blockIdx.z * bBatch;
    float* C = Cb + (long long)blockIdx.z * cBatch;
    const int bm0 = blockIdx.y * 128;
    const int bn0 = blockIdx.x * 128;

    int smoff[4];
    const float* aptr[4];
    const float* bptr[4];
    uint32_t bsz[4];
#pragma unroll
    for (int i = 0; i < 4; i++) {
        int idx = tid + i * 256;
        int r = idx >> 3;
        int c4 = idx & 7;
        smoff[i] = (r * LDT + c4 * 4) * 4;
        aptr[i] = A + (size_t)(bm0 + r) * lda + c4 * 4;
        bptr[i] = B + (size_t)(bn0 + r) * ldb + c4 * 4;
        bsz[i] = (bn0 + r < N) ? 16u : 0u;
    }

    const int a_off = ((wm * 64 + ((lane >> 3) & 1) * 8 + (lane & 7)) * LDT
                       + ((lane >> 4) << 2)) * 4;
    const int b_off = ((wn * 32 + ((lane >> 4) << 3) + (lane & 7)) * LDT
                       + (((lane >> 3) & 1) << 2)) * 4;

    float acc[4][4][4];
#pragma unroll
    for (int mt = 0; mt < 4; mt++)
#pragma unroll
        for (int nt = 0; nt < 4; nt++)
#pragma unroll
            for (int j = 0; j < 4; j++) acc[mt][nt][j] = 0.f;

    const int nsteps = K >> 5;
    // prologue: step 0 into buffer 0
    {
        uint32_t sb = su;
#pragma unroll
        for (int i = 0; i < 4; i++) CP_ASYNC(sb + smoff[i], aptr[i], 16u);
#pragma unroll
        for (int i = 0; i < 4; i++) CP_ASYNC(sb + TILE_FLOATS * 4 + smoff[i], bptr[i], bsz[i]);
        CP_COMMIT();
    }

    for (int s = 0; s < nsteps; s++) {
        CP_WAIT(0);
        __syncthreads();
        // issue next step's loads right after the barrier -> they overlap compute
        if (s + 1 < nsteps) {
            uint32_t sb = su + ((s + 1) & 1) * STAGE_BYTES;
            const int k0 = (s + 1) << 5;
#pragma unroll
            for (int i = 0; i < 4; i++) CP_ASYNC(sb + smoff[i], aptr[i] + k0, 16u);
#pragma unroll
            for (int i = 0; i < 4; i++) CP_ASYNC(sb + TILE_FLOATS * 4 + smoff[i], bptr[i] + k0, bsz[i]);
            CP_COMMIT();
        }

        const uint32_t sa = su + (s & 1) * STAGE_BYTES + a_off;
        const uint32_t sbb = su + (s & 1) * STAGE_BYTES + TILE_FLOATS * 4 + b_off;

#pragma unroll
        for (int kk = 0; kk < 4; kk++) {
            uint32_t a_regs[4][4], b_regs[2][4];
#pragma unroll
            for (int mt = 0; mt < 4; mt++)
                ldsm_x4(a_regs[mt], sa + (mt * 16 * LDT + kk * 8) * 4);
#pragma unroll
            for (int pr = 0; pr < 2; pr++)
                ldsm_x4(b_regs[pr], sbb + (pr * 16 * LDT + kk * 8) * 4);
#pragma unroll
            for (int mt = 0; mt < 4; mt++)
#pragma unroll
                for (int nt = 0; nt < 4; nt++)
                    mma_u(acc[mt][nt], a_regs[mt], &b_regs[nt >> 1][(nt & 1) * 2]);
        }
    }

    const bool has_bias = (bias != nullptr);
    const int gr = lane >> 2;
    const int gc = lane & 3;
#pragma unroll
    for (int mt = 0; mt < 4; mt++) {
        int r0 = bm0 + wm * 64 + mt * 16 + gr;
#pragma unroll
        for (int nt = 0; nt < 4; nt++) {
            int c0 = bn0 + wn * 32 + nt * 8 + gc * 2;
            if (c0 < N) {
                float bx = has_bias ? bias[c0] : 0.f;
                float by = has_bias ? bias[c0 + 1] : 0.f;
                float v00 = acc[mt][nt][0] + bx, v01 = acc[mt][nt][1] + by;
                float v10 = acc[mt][nt][2] + bx, v11 = acc[mt][nt][3] + by;
                if (round_out) {
                    v00 = rtf32(v00); v01 = rtf32(v01);
                    v10 = rtf32(v10); v11 = rtf32(v11);
                }
                *(float2*)&C[(size_t)r0 * ldc + c0] = make_float2(v00, v01);
                *(float2*)&C[(size_t)(r0 + 8) * ldc + c0] = make_float2(v10, v11);
            }
        }
    }
}

// ---------------- one-shot rounding + merging of all external operands ----------------
__device__ __forceinline__ void round_seg(const float* s, float* d, int n4,
                                          int gid, int gsz) {
    for (int i = gid; i < n4; i += gsz) {
        float4 v = ((const float4*)s)[i];
        v.x = rtf32(v.x); v.y = rtf32(v.y); v.z = rtf32(v.z); v.w = rtf32(v.w);
        ((float4*)d)[i] = v;
    }
}
__global__ __launch_bounds__(256) void round_all(
    const float* x, float* rx,
    const float* wqd, const float* wkvd, float* wd,
    const float* wqu, float* rwqu,
    const float* wku, const float* wvu, float* wuv,
    const float* wo, float* rwo,
    const float* bqd, const float* bkvd, float* bd,
    const float* bku, const float* bvu, float* buv)
{
    int gid = blockIdx.x * blockDim.x + threadIdx.x;
    int gsz = gridDim.x * blockDim.x;
    round_seg(x, rx, S_LEN * D_MODEL / 4, gid, gsz);
    round_seg(wqd, wd, CQ_DIM * D_MODEL / 4, gid, gsz);
    round_seg(wkvd, wd + CQ_DIM * D_MODEL, CKV_DIM * D_MODEL / 4, gid, gsz);
    round_seg(wqu, rwqu, NH * HDIM * CQ_DIM / 4, gid, gsz);
    round_seg(wku, wuv, NH * HDIM * CKV_DIM / 4, gid, gsz);
    round_seg(wvu, wuv + NH * HDIM * CKV_DIM, NH * HDIM * CKV_DIM / 4, gid, gsz);
    round_seg(wo, rwo, D_MODEL * NH * HDIM / 4, gid, gsz);
    for (int i = gid; i < NDOWN; i += gsz)
        bd[i] = (i < CQ_DIM) ? bqd[i] : bkvd[i - CQ_DIM];
    for (int i = gid; i < NUV; i += gsz)
        buv[i] = (i < 2048) ? bku[i] : bvu[i - 2048];
}

// ---------------- RoPE + hi/lo pack (K=384 concat) ----------------
// q from g_q (ld 2048); k from g_kv cols [0,2048) (ld 4096)
__global__ __launch_bounds__(256) void rope_pack(
    const float* __restrict__ q, const float* __restrict__ kv,
    const float* __restrict__ cosb, const float* __restrict__ sinb,
    float* __restrict__ qc, float* __restrict__ kc)
{
    int idx = blockIdx.x * blockDim.x + threadIdx.x;
    int dh = idx & 63;
    int t = idx >> 6;
    int h = t & (NH - 1);
    int s = t >> 4;
    if (s >= S_LEN) return;

    float c1 = cosb[s * HDIM + dh];
    float s1 = sinb[s * HDIM + dh];
    float c2 = cosb[s * HDIM + dh + 64];
    float s2 = sinb[s * HDIM + dh + 64];

    size_t qbase = (size_t)s * (NH * HDIM) + h * HDIM + dh;
    size_t kbase = (size_t)s * NUV + h * HDIM + dh;
    const float sc = 0.08838834764831845f;  // 1/sqrt(128)

    float q1 = q[qbase], q2 = q[qbase + 64];
    float qa = (q1 * c1 - q2 * s1) * sc;
    float qb = (q2 * c2 + q1 * s2) * sc;
    float k1 = kv[kbase], k2 = kv[kbase + 64];
    float ka = k1 * c1 - k2 * s1;
    float kb = k2 * c2 + k1 * s2;

    float qah, qal, qbh, qbl, kah, kal, kbh, kbl;
    split_hl(qa, qah, qal); split_hl(qb, qbh, qbl);
    split_hl(ka, kah, kal); split_hl(kb, kbh, kbl);

    size_t ob = ((size_t)h * S_LEN + s) * 384 + dh;
    qc[ob]       = qah; qc[ob + 64]       = qbh;
    qc[ob + 128] = qah; qc[ob + 128 + 64] = qbh;
    qc[ob + 256] = qal; qc[ob + 256 + 64] = qbl;
    kc[ob]       = kah; kc[ob + 64]       = kbh;
    kc[ob + 128] = kal; kc[ob + 128 + 64] = kbl;
    kc[ob + 256] = kah; kc[ob + 256 + 64] = kbh;
}

// ---------------- row softmax over 2048-wide rows, in place; rounds output ----------------
__global__ __launch_bounds__(256) void softmax_rows(float* __restrict__ L)
{
    __shared__ float red[8];
    float* p = L + (size_t)blockIdx.x * 2048;
    const int tid = threadIdx.x;
    const int wid = tid >> 5;
    const int lid = tid & 31;

    float4 a = ((const float4*)p)[tid];
    float4 b = ((const float4*)p)[tid + 256];

    float mx = fmaxf(fmaxf(fmaxf(a.x, a.y), fmaxf(a.z, a.w)),
                     fmaxf(fmaxf(b.x, b.y), fmaxf(b.z, b.w)));
#pragma unroll
    for (int m = 16; m > 0; m >>= 1) mx = fmaxf(mx, __shfl_xor_sync(~0u, mx, m));
    if (lid == 0) red[wid] = mx;
    __syncthreads();
    if (wid == 0) {
        float v = red[lid & 7];
#pragma unroll
        for (int m = 4; m > 0; m >>= 1) v = fmaxf(v, __shfl_xor_sync(~0u, v, m));
        if (lid == 0) red[0] = v;
    }
    __syncthreads();
    mx = red[0];
    __syncthreads();

    a.x = __expf(a.x - mx); a.y = __expf(a.y - mx); a.z = __expf(a.z - mx); a.w = __expf(a.w - mx);
    b.x = __expf(b.x - mx); b.y = __expf(b.y - mx); b.z = __expf(b.z - mx); b.w = __expf(b.w - mx);
    float sm = a.x + a.y + a.z + a.w + b.x + b.y + b.z + b.w;
#pragma unroll
    for (int m = 16; m > 0; m >>= 1) sm += __shfl_xor_sync(~0u, sm, m);
    if (lid == 0) red[wid] = sm;
    __syncthreads();
    if (wid == 0) {
        float v = red[lid & 7];
#pragma unroll
        for (int m = 4; m > 0; m >>= 1) v += __shfl_xor_sync(~0u, v, m);
        if (lid == 0) red[0] = v;
    }
    __syncthreads();
    const float inv = 1.f / red[0];

    a.x = rtf32(a.x * inv); a.y = rtf32(a.y * inv); a.z = rtf32(a.z * inv); a.w = rtf32(a.w * inv);
    b.x = rtf32(b.x * inv); b.y = rtf32(b.y * inv); b.z = rtf32(b.z * inv); b.w = rtf32(b.w * inv);
    ((float4*)p)[tid] = a;
    ((float4*)p)[tid + 256] = b;
}

// ---------------- 2048x2048 transpose with strides, rounds output ----------------
__global__ void transpose2048(const float* __restrict__ src, float* __restrict__ dst,
                              int lds, int ldd)
{
    __shared__ float t[32][33];
    int x = threadIdx.x, y = threadIdx.y;
    int r0 = blockIdx.y * 32, c0 = blockIdx.x * 32;
#pragma unroll
    for (int i = 0; i < 32; i += 8)
        t[y + i][x] = src[(size_t)(r0 + y + i) * lds + c0 + x];
    __syncthreads();
#pragma unroll
    for (int i = 0; i < 32; i += 8)
        dst[(size_t)(c0 + y + i) * ldd + r0 + x] = rtf32(t[x][y + i]);
}

// ---------------- launch ----------------
extern "C" void kernel_launch(void* const* d_in, const int* in_sizes, int n_in,
                              void* d_out, int out_size)
{
    const float* x        = (const float*)d_in[0];
    const float* rope_cos = (const float*)d_in[1];
    const float* rope_sin = (const float*)d_in[2];
    const float* wq_down  = (const float*)d_in[3];
    const float* bq_down  = (const float*)d_in[4];
    const float* wq_up    = (const float*)d_in[5];
    const float* bq_up    = (const float*)d_in[6];
    const float* wkv_down = (const float*)d_in[7];
    const float* bkv_down = (const float*)d_in[8];
    const float* wk_up    = (const float*)d_in[9];
    const float* bk_up    = (const float*)d_in[10];
    const float* wv_up    = (const float*)d_in[11];
    const float* bv_up    = (const float*)d_in[12];
    const float* wo       = (const float*)d_in[13];
    const float* bo       = (const float*)d_in[14];
    float* out = (float*)d_out;

    float *cqkv, *q, *kv, *vt, *attn, *qc, *kc, *logits;
    float *rx, *wd, *bd, *rwqu, *wuv, *buv, *rwo;
    cudaGetSymbolAddress((void**)&cqkv,   g_cqkv);
    cudaGetSymbolAddress((void**)&q,      g_q);
    cudaGetSymbolAddress((void**)&kv,     g_kv);
    cudaGetSymbolAddress((void**)&vt,     g_vt);
    cudaGetSymbolAddress((void**)&attn,   g_attn);
    cudaGetSymbolAddress((void**)&qc,     g_qc);
    cudaGetSymbolAddress((void**)&kc,     g_kc);
    cudaGetSymbolAddress((void**)&logits, g_logits);
    cudaGetSymbolAddress((void**)&rx,     g_x);
    cudaGetSymbolAddress((void**)&wd,     g_wd);
    cudaGetSymbolAddress((void**)&bd,     g_bd);
    cudaGetSymbolAddress((void**)&rwqu,   g_wqu);
    cudaGetSymbolAddress((void**)&wuv,    g_wuv);
    cudaGetSymbolAddress((void**)&buv,    g_buv);
    cudaGetSymbolAddress((void**)&rwo,    g_wo);

    cudaFuncSetAttribute(gemm_mma, cudaFuncAttributeMaxDynamicSharedMemorySize, GEMM_SMEM);

    const long long SS = (long long)S_LEN * S_LEN;
    const long long S384 = (long long)S_LEN * 384;

    // 0: round + merge all external operands
    round_all<<<512, 256>>>(x, rx, wq_down, wkv_down, wd, wq_up, rwqu,
                            wk_up, wv_up, wuv, wo, rwo,
                            bq_down, bkv_down, bd, bk_up, bv_up, buv);

    // 1: [c_q | c_kv] = x @ [wq_down; wkv_down]^T + b    [2048, 608]  (rounded)
    gemm_mma<<<dim3(5, 16, 1), 256, GEMM_SMEM>>>(
        rx, wd, bd, cqkv, NDOWN, D_MODEL, D_MODEL, D_MODEL, NDOWN, 0, 0, 0, 1);
    // 2: q = c_q @ wq_up^T + b                            [2048, 2048]
    gemm_mma<<<dim3(16, 16, 1), 256, GEMM_SMEM>>>(
        cqkv, rwqu, bq_up, q, 2048, CQ_DIM, NDOWN, CQ_DIM, 2048, 0, 0, 0, 0);
    // 3: [k | v] = c_kv @ [wk_up; wv_up]^T + b            [2048, 4096]
    gemm_mma<<<dim3(32, 16, 1), 256, GEMM_SMEM>>>(
        cqkv + CQ_DIM, wuv, buv, kv, NUV, CKV_DIM, NDOWN, CKV_DIM, NUV, 0, 0, 0, 0);

    // 4: rope + hi/lo pack
    rope_pack<<<(S_LEN * NH * 64) / 256, 256>>>(q, kv, rope_cos, rope_sin, qc, kc);

    // 5: logits[h] = Q'_h @ K'_h^T   (K=384 concat == tf32x3 precision)  <- ncu slot
    gemm_mma<<<dim3(16, 16, NH), 256, GEMM_SMEM>>>(
        qc, kc, nullptr, logits, 2048, 384, 384, 384, 2048, S384, S384, SS, 0);

    // 6: softmax rows (rounds output to tf32)
    softmax_rows<<<NH * S_LEN, 256>>>(logits);

    // 7: v^T  (v = g_kv cols [2048,4096), ld 4096 -> vt ld 2048, rounded)
    transpose2048<<<dim3(64, 64), dim3(32, 8)>>>(kv + 2048, vt, NUV, 2048);

    // 8: attn per head: M=2048, N=128, K=2048 (rounded out)
    gemm_mma<<<dim3(1, 16, NH), 256, GEMM_SMEM>>>(
        logits, vt, nullptr, attn, HDIM, 2048, 2048, 2048, 2048,
        SS, (long long)HDIM * 2048, HDIM, 1);

    // 9: out = attn @ wo^T + bo                           [2048, 2048]
    gemm_mma<<<dim3(16, 16, 1), 256, GEMM_SMEM>>>(
        attn, rwo, bo, out, 2048, 2048, 2048, 2048, 2048, 0, 0, 0, 0);
}

// round 15
// speedup vs baseline: 1.7150x; 1.2056x over previous
#include <cuda_runtime.h>
#include <cuda_bf16.h>
#include <cstdint>

#define S_LEN 2048
#define D_MODEL 2048
#define NH 16
#define HDIM 128
#define CQ_DIM 96
#define CKV_DIM 512
#define NDOWN 608                 // 96 + 512
#define NUV 4096                  // 2048 + 2048

// ---------------- scratch (static device memory; no allocations) ----------------
__device__ float g_cqkv[S_LEN * NDOWN];                   // [s][cq|ckv]
__device__ float g_q[S_LEN * NH * HDIM];
__device__ float g_kv[S_LEN * NUV];                       // [s][k(2048)|v(2048)]
__device__ float g_vt[S_LEN * NH * HDIM];
__device__ float g_attn[S_LEN * NH * HDIM];
__device__ __nv_bfloat16 g_qcb[NH * S_LEN * 384];         // [h][s][qhi|qhi|qlo]
__device__ __nv_bfloat16 g_kcb[NH * S_LEN * 384];         // [h][s][khi|klo|khi]
__device__ float g_logits[(long long)NH * S_LEN * S_LEN]; // 256 MB
// rounded/merged copies of external inputs
__device__ float g_x[S_LEN * D_MODEL];
__device__ float g_wd[NDOWN * D_MODEL];                   // [wq_down; wkv_down]
__device__ float g_bd[NDOWN];
__device__ float g_wqu[(NH * HDIM) * CQ_DIM];
__device__ float g_wuv[NUV * CKV_DIM];                    // [wk_up; wv_up]
__device__ float g_buv[NUV];
__device__ float g_wo[D_MODEL * (NH * HDIM)];

// ---------------- helpers ----------------
__device__ __forceinline__ uint32_t smem_u32(const void* p) {
    uint32_t a;
    asm("{ .reg .u64 t; cvta.to.shared.u64 t, %1; cvt.u32.u64 %0, t; }" : "=r"(a) : "l"(p));
    return a;
}
__device__ __forceinline__ float rtf32(float x) {
    uint32_t u;
    asm("cvt.rna.tf32.f32 %0, %1;" : "=r"(u) : "f"(x));
    return __uint_as_float(u);
}
#define CP_ASYNC(dst, src, sz) \
    asm volatile("cp.async.cg.shared.global [%0], [%1], 16, %2;" \
        :: "r"(dst), "l"(src), "r"(sz) : "memory")
#define CP_COMMIT() asm volatile("cp.async.commit_group;" ::: "memory")
#define CP_WAIT(n)  asm volatile("cp.async.wait_group %0;" :: "n"(n) : "memory")

__device__ __forceinline__ void mma_u(float* c, const uint32_t* a, const uint32_t* b) {
    asm volatile(
        "mma.sync.aligned.m16n8k8.row.col.f32.tf32.tf32.f32 "
        "{%0,%1,%2,%3}, {%4,%5,%6,%7}, {%8,%9}, {%0,%1,%2,%3};"
        : "+f"(c[0]), "+f"(c[1]), "+f"(c[2]), "+f"(c[3])
        : "r"(a[0]), "r"(a[1]), "r"(a[2]), "r"(a[3]), "r"(b[0]), "r"(b[1]));
}
__device__ __forceinline__ void mma_bf16(float* c, const uint32_t* a, const uint32_t* b) {
    asm volatile(
        "mma.sync.aligned.m16n8k16.row.col.f32.bf16.bf16.f32 "
        "{%0,%1,%2,%3}, {%4,%5,%6,%7}, {%8,%9}, {%0,%1,%2,%3};"
        : "+f"(c[0]), "+f"(c[1]), "+f"(c[2]), "+f"(c[3])
        : "r"(a[0]), "r"(a[1]), "r"(a[2]), "r"(a[3]), "r"(b[0]), "r"(b[1]));
}
__device__ __forceinline__ void ldsm_x4(uint32_t* r, uint32_t addr) {
    asm volatile("ldmatrix.sync.aligned.m8n8.x4.shared.b16 {%0,%1,%2,%3}, [%4];"
        : "=r"(r[0]), "=r"(r[1]), "=r"(r[2]), "=r"(r[3]) : "r"(addr));
}

// ---------------- shared tile geometry (byte-identical for fp32/bf16 kernels) ----
#define LDT 36                                   // fp32 elems per padded row (144 B)
#define ROW_BYTES 144
#define TILE_BYTES (128 * ROW_BYTES)             // 18432
#define STAGE_BYTES (2 * TILE_BYTES)             // A + B
#define GEMM_SMEM (2 * STAGE_BYTES)              // 2 stages

// ---------------- tf32 mma.sync GEMM: C = A[M,K] @ B[N,K]^T (+bias) ----------------
__global__ __launch_bounds__(256, 2) void gemm_mma(
    const float* __restrict__ Ab, const float* __restrict__ Bb,
    const float* __restrict__ bias, float* __restrict__ Cb,
    int N, int K, int lda, int ldb, int ldc,
    long long aBatch, long long bBatch, long long cBatch, int round_out)
{
    extern __shared__ char smem[];
    const uint32_t su = smem_u32(smem);

    const int tid = threadIdx.x;
    const int warp = tid >> 5;
    const int lane = tid & 31;
    const int wm = warp & 1;
    const int wn = warp >> 1;
    const float* A = Ab + (long long)blockIdx.z * aBatch;
    const float* B = Bb + (long long)blockIdx.z * bBatch;
    float* C = Cb + (long long)blockIdx.z * cBatch;
    const int bm0 = blockIdx.y * 128;
    const int bn0 = blockIdx.x * 128;

    int smoff[4];
    const float* aptr[4];
    const float* bptr[4];
    uint32_t bsz[4];
#pragma unroll
    for (int i = 0; i < 4; i++) {
        int idx = tid + i * 256;
        int r = idx >> 3;
        int c4 = idx & 7;
        smoff[i] = r * ROW_BYTES + c4 * 16;
        aptr[i] = A + (size_t)(bm0 + r) * lda + c4 * 4;
        bptr[i] = B + (size_t)(bn0 + r) * ldb + c4 * 4;
        bsz[i] = (bn0 + r < N) ? 16u : 0u;
    }

    const int a_off = (wm * 64 + ((lane >> 3) & 1) * 8 + (lane & 7)) * ROW_BYTES
                      + (lane >> 4) * 16;
    const int b_off = (wn * 32 + ((lane >> 4) << 3) + (lane & 7)) * ROW_BYTES
                      + (((lane >> 3) & 1)) * 16;

    float acc[4][4][4];
#pragma unroll
    for (int mt = 0; mt < 4; mt++)
#pragma unroll
        for (int nt = 0; nt < 4; nt++)
#pragma unroll
            for (int j = 0; j < 4; j++) acc[mt][nt][j] = 0.f;

    const int nsteps = K >> 5;
    {
        uint32_t sb = su;
#pragma unroll
        for (int i = 0; i < 4; i++) CP_ASYNC(sb + smoff[i], aptr[i], 16u);
#pragma unroll
        for (int i = 0; i < 4; i++) CP_ASYNC(sb + TILE_BYTES + smoff[i], bptr[i], bsz[i]);
        CP_COMMIT();
    }

    for (int s = 0; s < nsteps; s++) {
        CP_WAIT(0);
        __syncthreads();
        if (s + 1 < nsteps) {
            uint32_t sb = su + ((s + 1) & 1) * STAGE_BYTES;
            const int k0 = (s + 1) << 5;
#pragma unroll
            for (int i = 0; i < 4; i++) CP_ASYNC(sb + smoff[i], aptr[i] + k0, 16u);
#pragma unroll
            for (int i = 0; i < 4; i++) CP_ASYNC(sb + TILE_BYTES + smoff[i], bptr[i] + k0, bsz[i]);
            CP_COMMIT();
        }

        const uint32_t sa = su + (s & 1) * STAGE_BYTES + a_off;
        const uint32_t sbb = su + (s & 1) * STAGE_BYTES + TILE_BYTES + b_off;

#pragma unroll
        for (int kk = 0; kk < 4; kk++) {
            uint32_t a_regs[4][4], b_regs[2][4];
#pragma unroll
            for (int mt = 0; mt < 4; mt++)
                ldsm_x4(a_regs[mt], sa + mt * 16 * ROW_BYTES + kk * 32);
#pragma unroll
            for (int pr = 0; pr < 2; pr++)
                ldsm_x4(b_regs[pr], sbb + pr * 16 * ROW_BYTES + kk * 32);
#pragma unroll
            for (int mt = 0; mt < 4; mt++)
#pragma unroll
                for (int nt = 0; nt < 4; nt++)
                    mma_u(acc[mt][nt], a_regs[mt], &b_regs[nt >> 1][(nt & 1) * 2]);
        }
    }

    const bool has_bias = (bias != nullptr);
    const int gr = lane >> 2;
    const int gc = lane & 3;
#pragma unroll
    for (int mt = 0; mt < 4; mt++) {
        int r0 = bm0 + wm * 64 + mt * 16 + gr;
#pragma unroll
        for (int nt = 0; nt < 4; nt++) {
            int c0 = bn0 + wn * 32 + nt * 8 + gc * 2;
            if (c0 < N) {
                float bx = has_bias ? bias[c0] : 0.f;
                float by = has_bias ? bias[c0 + 1] : 0.f;
                float v00 = acc[mt][nt][0] + bx, v01 = acc[mt][nt][1] + by;
                float v10 = acc[mt][nt][2] + bx, v11 = acc[mt][nt][3] + by;
                if (round_out) {
                    v00 = rtf32(v00); v01 = rtf32(v01);
                    v10 = rtf32(v10); v11 = rtf32(v11);
                }
                *(float2*)&C[(size_t)r0 * ldc + c0] = make_float2(v00, v01);
                *(float2*)&C[(size_t)(r0 + 8) * ldc + c0] = make_float2(v10, v11);
            }
        }
    }
}

// ---------------- bf16 mma.sync GEMM (m16n8k16): C = A[M,K] @ B[N,K]^T ----------------
// Same byte-level smem layout as gemm_mma; BK=64 bf16 per step (128 B rows).
__global__ __launch_bounds__(256, 2) void gemm_bf16(
    const __nv_bfloat16* __restrict__ Ab, const __nv_bfloat16* __restrict__ Bb,
    float* __restrict__ Cb,
    int N, int K, int lda, int ldb, int ldc,
    long long aBatch, long long bBatch, long long cBatch)
{
    extern __shared__ char smem[];
    const uint32_t su = smem_u32(smem);

    const int tid = threadIdx.x;
    const int warp = tid >> 5;
    const int lane = tid & 31;
    const int wm = warp & 1;
    const int wn = warp >> 1;
    const __nv_bfloat16* A = Ab + (long long)blockIdx.z * aBatch;
    const __nv_bfloat16* B = Bb + (long long)blockIdx.z * bBatch;
    float* C = Cb + (long long)blockIdx.z * cBatch;
    const int bm0 = blockIdx.y * 128;
    const int bn0 = blockIdx.x * 128;

    int smoff[4];
    const __nv_bfloat16* aptr[4];
    const __nv_bfloat16* bptr[4];
#pragma unroll
    for (int i = 0; i < 4; i++) {
        int idx = tid + i * 256;
        int r = idx >> 3;
        int c4 = idx & 7;                  // 8 x 16B chunks = 64 bf16 per row
        smoff[i] = r * ROW_BYTES + c4 * 16;
        aptr[i] = A + (size_t)(bm0 + r) * lda + c4 * 8;
        bptr[i] = B + (size_t)(bn0 + r) * ldb + c4 * 8;
    }

    const int a_off = (wm * 64 + ((lane >> 3) & 1) * 8 + (lane & 7)) * ROW_BYTES
                      + (lane >> 4) * 16;
    const int b_off = (wn * 32 + ((lane >> 4) << 3) + (lane & 7)) * ROW_BYTES
                      + (((lane >> 3) & 1)) * 16;

    float acc[4][4][4];
#pragma unroll
    for (int mt = 0; mt < 4; mt++)
#pragma unroll
        for (int nt = 0; nt < 4; nt++)
#pragma unroll
            for (int j = 0; j < 4; j++) acc[mt][nt][j] = 0.f;

    const int nsteps = K >> 6;             // BK = 64 bf16
    {
        uint32_t sb = su;
#pragma unroll
        for (int i = 0; i < 4; i++) CP_ASYNC(sb + smoff[i], aptr[i], 16u);
#pragma unroll
        for (int i = 0; i < 4; i++) CP_ASYNC(sb + TILE_BYTES + smoff[i], bptr[i], 16u);
        CP_COMMIT();
    }

    for (int s = 0; s < nsteps; s++) {
        CP_WAIT(0);
        __syncthreads();
        if (s + 1 < nsteps) {
            uint32_t sb = su + ((s + 1) & 1) * STAGE_BYTES;
            const int k0 = (s + 1) << 6;
#pragma unroll
            for (int i = 0; i < 4; i++) CP_ASYNC(sb + smoff[i], aptr[i] + k0, 16u);
#pragma unroll
            for (int i = 0; i < 4; i++) CP_ASYNC(sb + TILE_BYTES + smoff[i], bptr[i] + k0, 16u);
            CP_COMMIT();
        }

        const uint32_t sa = su + (s & 1) * STAGE_BYTES + a_off;
        const uint32_t sbb = su + (s & 1) * STAGE_BYTES + TILE_BYTES + b_off;

#pragma unroll
        for (int kk = 0; kk < 4; kk++) {   // 4 x k16 = 64 bf16
            uint32_t a_regs[4][4], b_regs[2][4];
#pragma unroll
            for (int mt = 0; mt < 4; mt++)
                ldsm_x4(a_regs[mt], sa + mt * 16 * ROW_BYTES + kk * 32);
#pragma unroll
            for (int pr = 0; pr < 2; pr++)
                ldsm_x4(b_regs[pr], sbb + pr * 16 * ROW_BYTES + kk * 32);
#pragma unroll
            for (int mt = 0; mt < 4; mt++)
#pragma unroll
                for (int nt = 0; nt < 4; nt++)
                    mma_bf16(acc[mt][nt], a_regs[mt], &b_regs[nt >> 1][(nt & 1) * 2]);
        }
    }

    const int gr = lane >> 2;
    const int gc = lane & 3;
#pragma unroll
    for (int mt = 0; mt < 4; mt++) {
        int r0 = bm0 + wm * 64 + mt * 16 + gr;
#pragma unroll
        for (int nt = 0; nt < 4; nt++) {
            int c0 = bn0 + wn * 32 + nt * 8 + gc * 2;
            *(float2*)&C[(size_t)r0 * ldc + c0] = make_float2(acc[mt][nt][0], acc[mt][nt][1]);
            *(float2*)&C[(size_t)(r0 + 8) * ldc + c0] = make_float2(acc[mt][nt][2], acc[mt][nt][3]);
        }
    }
}

// ---------------- one-shot rounding + merging of all external operands ----------------
__device__ __forceinline__ void round_seg(const float* s, float* d, int n4,
                                          int gid, int gsz) {
    for (int i = gid; i < n4; i += gsz) {
        float4 v = ((const float4*)s)[i];
        v.x = rtf32(v.x); v.y = rtf32(v.y); v.z = rtf32(v.z); v.w = rtf32(v.w);
        ((float4*)d)[i] = v;
    }
}
__global__ __launch_bounds__(256) void round_all(
    const float* x, float* rx,
    const float* wqd, const float* wkvd, float* wd,
    const float* wqu, float* rwqu,
    const float* wku, const float* wvu, float* wuv,
    const float* wo, float* rwo,
    const float* bqd, const float* bkvd, float* bd,
    const float* bku, const float* bvu, float* buv)
{
    int gid = blockIdx.x * blockDim.x + threadIdx.x;
    int gsz = gridDim.x * blockDim.x;
    round_seg(x, rx, S_LEN * D_MODEL / 4, gid, gsz);
    round_seg(wqd, wd, CQ_DIM * D_MODEL / 4, gid, gsz);
    round_seg(wkvd, wd + CQ_DIM * D_MODEL, CKV_DIM * D_MODEL / 4, gid, gsz);
    round_seg(wqu, rwqu, NH * HDIM * CQ_DIM / 4, gid, gsz);
    round_seg(wku, wuv, NH * HDIM * CKV_DIM / 4, gid, gsz);
    round_seg(wvu, wuv + NH * HDIM * CKV_DIM, NH * HDIM * CKV_DIM / 4, gid, gsz);
    round_seg(wo, rwo, D_MODEL * NH * HDIM / 4, gid, gsz);
    for (int i = gid; i < NDOWN; i += gsz)
        bd[i] = (i < CQ_DIM) ? bqd[i] : bkvd[i - CQ_DIM];
    for (int i = gid; i < NUV; i += gsz)
        buv[i] = (i < 2048) ? bku[i] : bvu[i - 2048];
}

// ---------------- RoPE + bf16 hi/lo pack (K=384 concat) ----------------
__global__ __launch_bounds__(256) void rope_pack(
    const float* __restrict__ q, const float* __restrict__ kv,
    const float* __restrict__ cosb, const float* __restrict__ sinb,
    __nv_bfloat16* __restrict__ qc, __nv_bfloat16* __restrict__ kc)
{
    int idx = blockIdx.x * blockDim.x + threadIdx.x;
    int dh = idx & 63;
    int t = idx >> 6;
    int h = t & (NH - 1);
    int s = t >> 4;
    if (s >= S_LEN) return;

    float c1 = cosb[s * HDIM + dh];
    float s1 = sinb[s * HDIM + dh];
    float c2 = cosb[s * HDIM + dh + 64];
    float s2 = sinb[s * HDIM + dh + 64];

    size_t qbase = (size_t)s * (NH * HDIM) + h * HDIM + dh;
    size_t kbase = (size_t)s * NUV + h * HDIM + dh;
    const float sc = 0.08838834764831845f;  // 1/sqrt(128)

    float q1 = q[qbase], q2 = q[qbase + 64];
    float qa = (q1 * c1 - q2 * s1) * sc;
    float qb = (q2 * c2 + q1 * s2) * sc;
    float k1 = kv[kbase], k2 = kv[kbase + 64];
    float ka = k1 * c1 - k2 * s1;
    float kb = k2 * c2 + k1 * s2;

    __nv_bfloat16 qah = __float2bfloat16_rn(qa);
    __nv_bfloat16 qal = __float2bfloat16_rn(qa - __bfloat162float(qah));
    __nv_bfloat16 qbh = __float2bfloat16_rn(qb);
    __nv_bfloat16 qbl = __float2bfloat16_rn(qb - __bfloat162float(qbh));
    __nv_bfloat16 kah = __float2bfloat16_rn(ka);
    __nv_bfloat16 kal = __float2bfloat16_rn(ka - __bfloat162float(kah));
    __nv_bfloat16 kbh = __float2bfloat16_rn(kb);
    __nv_bfloat16 kbl = __float2bfloat16_rn(kb - __bfloat162float(kbh));

    size_t ob = ((size_t)h * S_LEN + s) * 384 + dh;
    qc[ob]       = qah; qc[ob + 64]       = qbh;
    qc[ob + 128] = qah; qc[ob + 128 + 64] = qbh;
    qc[ob + 256] = qal; qc[ob + 256 + 64] = qbl;
    kc[ob]       = kah; kc[ob + 64]       = kbh;
    kc[ob + 128] = kal; kc[ob + 128 + 64] = kbl;
    kc[ob + 256] = kah; kc[ob + 256 + 64] = kbh;
}

// ---------------- row softmax over 2048-wide rows, in place; rounds output ----------------
__global__ __launch_bounds__(256) void softmax_rows(float* __restrict__ L)
{
    __shared__ float red[8];
    float* p = L + (size_t)blockIdx.x * 2048;
    const int tid = threadIdx.x;
    const int wid = tid >> 5;
    const int lid = tid & 31;

    float4 a = ((const float4*)p)[tid];
    float4 b = ((const float4*)p)[tid + 256];

    float mx = fmaxf(fmaxf(fmaxf(a.x, a.y), fmaxf(a.z, a.w)),
                     fmaxf(fmaxf(b.x, b.y), fmaxf(b.z, b.w)));
#pragma unroll
    for (int m = 16; m > 0; m >>= 1) mx = fmaxf(mx, __shfl_xor_sync(~0u, mx, m));
    if (lid == 0) red[wid] = mx;
    __syncthreads();
    if (wid == 0) {
        float v = red[lid & 7];
#pragma unroll
        for (int m = 4; m > 0; m >>= 1) v = fmaxf(v, __shfl_xor_sync(~0u, v, m));
        if (lid == 0) red[0] = v;
    }
    __syncthreads();
    mx = red[0];
    __syncthreads();

    a.x = __expf(a.x - mx); a.y = __expf(a.y - mx); a.z = __expf(a.z - mx); a.w = __expf(a.w - mx);
    b.x = __expf(b.x - mx); b.y = __expf(b.y - mx); b.z = __expf(b.z - mx); b.w = __expf(b.w - mx);
    float sm = a.x + a.y + a.z + a.w + b.x + b.y + b.z + b.w;
#pragma unroll
    for (int m = 16; m > 0; m >>= 1) sm += __shfl_xor_sync(~0u, sm, m);
    if (lid == 0) red[wid] = sm;
    __syncthreads();
    if (wid == 0) {
        float v = red[lid & 7];
#pragma unroll
        for (int m = 4; m > 0; m >>= 1) v += __shfl_xor_sync(~0u, v, m);
        if (lid == 0) red[0] = v;
    }
    __syncthreads();
    const float inv = 1.f / red[0];

    a.x = rtf32(a.x * inv); a.y = rtf32(a.y * inv); a.z = rtf32(a.z * inv); a.w = rtf32(a.w * inv);
    b.x = rtf32(b.x * inv); b.y = rtf32(b.y * inv); b.z = rtf32(b.z * inv); b.w = rtf32(b.w * inv);
    ((float4*)p)[tid] = a;
    ((float4*)p)[tid + 256] = b;
}

// ---------------- transpose with strides, rounds output ----------------
__global__ void transpose2048(const float* __restrict__ src, float* __restrict__ dst,
                              int lds, int ldd)
{
    __shared__ float t[32][33];
    int x = threadIdx.x, y = threadIdx.y;
    int r0 = blockIdx.y * 32, c0 = blockIdx.x * 32;
#pragma unroll
    for (int i = 0; i < 32; i += 8)
        t[y + i][x] = src[(size_t)(r0 + y + i) * lds + c0 + x];
    __syncthreads();
#pragma unroll
    for (int i = 0; i < 32; i += 8)
        dst[(size_t)(c0 + y + i) * ldd + r0 + x] = rtf32(t[x][y + i]);
}

// ---------------- launch ----------------
extern "C" void kernel_launch(void* const* d_in, const int* in_sizes, int n_in,
                              void* d_out, int out_size)
{
    const float* x        = (const float*)d_in[0];
    const float* rope_cos = (const float*)d_in[1];
    const float* rope_sin = (const float*)d_in[2];
    const float* wq_down  = (const float*)d_in[3];
    const float* bq_down  = (const float*)d_in[4];
    const float* wq_up    = (const float*)d_in[5];
    const float* bq_up    = (const float*)d_in[6];
    const float* wkv_down = (const float*)d_in[7];
    const float* bkv_down = (const float*)d_in[8];
    const float* wk_up    = (const float*)d_in[9];
    const float* bk_up    = (const float*)d_in[10];
    const float* wv_up    = (const float*)d_in[11];
    const float* bv_up    = (const float*)d_in[12];
    const float* wo       = (const float*)d_in[13];
    const float* bo       = (const float*)d_in[14];
    float* out = (float*)d_out;

    float *cqkv, *q, *kv, *vt, *attn, *logits;
    __nv_bfloat16 *qcb, *kcb;
    float *rx, *wd, *bd, *rwqu, *wuv, *buv, *rwo;
    cudaGetSymbolAddress((void**)&cqkv,   g_cqkv);
    cudaGetSymbolAddress((void**)&q,      g_q);
    cudaGetSymbolAddress((void**)&kv,     g_kv);
    cudaGetSymbolAddress((void**)&vt,     g_vt);
    cudaGetSymbolAddress((void**)&attn,   g_attn);
    cudaGetSymbolAddress((void**)&qcb,    g_qcb);
    cudaGetSymbolAddress((void**)&kcb,    g_kcb);
    cudaGetSymbolAddress((void**)&logits, g_logits);
    cudaGetSymbolAddress((void**)&rx,     g_x);
    cudaGetSymbolAddress((void**)&wd,     g_wd);
    cudaGetSymbolAddress((void**)&bd,     g_bd);
    cudaGetSymbolAddress((void**)&rwqu,   g_wqu);
    cudaGetSymbolAddress((void**)&wuv,    g_wuv);
    cudaGetSymbolAddress((void**)&buv,    g_buv);
    cudaGetSymbolAddress((void**)&rwo,    g_wo);

    cudaFuncSetAttribute(gemm_mma, cudaFuncAttributeMaxDynamicSharedMemorySize, GEMM_SMEM);
    cudaFuncSetAttribute(gemm_bf16, cudaFuncAttributeMaxDynamicSharedMemorySize, GEMM_SMEM);

    const long long SS = (long long)S_LEN * S_LEN;
    const long long S384 = (long long)S_LEN * 384;

    // 0: round + merge all external operands
    round_all<<<512, 256>>>(x, rx, wq_down, wkv_down, wd, wq_up, rwqu,
                            wk_up, wv_up, wuv, wo, rwo,
                            bq_down, bkv_down, bd, bk_up, bv_up, buv);

    // 1: [c_q | c_kv] = x @ [wq_down; wkv_down]^T + b    [2048, 608]  (rounded)
    gemm_mma<<<dim3(5, 16, 1), 256, GEMM_SMEM>>>(
        rx, wd, bd, cqkv, NDOWN, D_MODEL, D_MODEL, D_MODEL, NDOWN, 0, 0, 0, 1);
    // 2: q = c_q @ wq_up^T + b                            [2048, 2048]
    gemm_mma<<<dim3(16, 16, 1), 256, GEMM_SMEM>>>(
        cqkv, rwqu, bq_up, q, 2048, CQ_DIM, NDOWN, CQ_DIM, 2048, 0, 0, 0, 0);
    // 3: [k | v] = c_kv @ [wk_up; wv_up]^T + b            [2048, 4096]
    gemm_mma<<<dim3(32, 16, 1), 256, GEMM_SMEM>>>(
        cqkv + CQ_DIM, wuv, buv, kv, NUV, CKV_DIM, NDOWN, CKV_DIM, NUV, 0, 0, 0, 0);

    // 4: rope + bf16 hi/lo pack
    rope_pack<<<(S_LEN * NH * 64) / 256, 256>>>(q, kv, rope_cos, rope_sin, qcb, kcb);

    // 5: logits[h] = Q'_h @ K'_h^T  (bf16 3-term concat, K=384, k16 MMAs)
    gemm_bf16<<<dim3(16, 16, NH), 256, GEMM_SMEM>>>(
        qcb, kcb, logits, 2048, 384, 384, 384, 2048, S384, S384, SS);

    // 6: softmax rows (rounds output to tf32)
    softmax_rows<<<NH * S_LEN, 256>>>(logits);

    // 7: v^T  (v = g_kv cols [2048,4096), ld 4096 -> vt ld 2048, rounded)
    transpose2048<<<dim3(64, 64), dim3(32, 8)>>>(kv + 2048, vt, NUV, 2048);

    // 8: attn per head: M=2048, N=128, K=2048 (rounded out)
    gemm_mma<<<dim3(1, 16, NH), 256, GEMM_SMEM>>>(
        logits, vt, nullptr, attn, HDIM, 2048, 2048, 2048, 2048,
        SS, (long long)HDIM * 2048, HDIM, 1);

    // 9: out = attn @ wo^T + bo                           [2048, 2048]
    gemm_mma<<<dim3(16, 16, 1), 256, GEMM_SMEM>>>(
        attn, rwo, bo, out, 2048, 2048, 2048, 2048, 2048, 0, 0, 0, 0);
}

// round 17
// speedup vs baseline: 2.2607x; 1.3182x over previous
#include <cuda_runtime.h>
#include <cuda_bf16.h>
#include <cuda_fp16.h>
#include <cstdint>

#define S_LEN 2048
#define D_MODEL 2048
#define NH 16
#define HDIM 128
#define CQ_DIM 96
#define CKV_DIM 512
#define NDOWNP 640                // 96 cq + 32 pad + 512 ckv
#define NUV 4096

// ---------------- scratch (static device memory; no allocations) ----------------
__device__ __half g_xh[S_LEN * D_MODEL];
__device__ __half g_wdh[NDOWNP * D_MODEL];        // rows: [wq_down(96) | zero(32) | wkv_down(512)]
__device__ float  g_bdm[NDOWNP];
__device__ __half g_wquh[(NH * HDIM) * 128];      // cols 96..128 zero
__device__ __half g_wuvh[NUV * CKV_DIM];          // [wk_up; wv_up]
__device__ float  g_buvm[NUV];
__device__ __half g_woh[D_MODEL * (NH * HDIM)];
__device__ __half g_cqkvh[S_LEN * NDOWNP];        // [s][cq96|pad32|ckv512]
__device__ float  g_q[S_LEN * NH * HDIM];
__device__ float  g_kv[S_LEN * NUV];              // [s][k|v]
__device__ __nv_bfloat16 g_qcb[NH * S_LEN * 384]; // [h][s][qhi|qhi|qlo]
__device__ __nv_bfloat16 g_kcb[NH * S_LEN * 384]; // [h][s][khi|klo|khi]
__device__ float  g_logits[(long long)NH * S_LEN * S_LEN]; // 256 MB
__device__ __half g_Ph[(long long)NH * S_LEN * S_LEN];     // 134 MB softmax out
__device__ __half g_vth[NH * HDIM * S_LEN];       // [h][d][s]
__device__ __half g_attnh[S_LEN * NH * HDIM];

// ---------------- helpers ----------------
__device__ __forceinline__ uint32_t smem_u32(const void* p) {
    uint32_t a;
    asm("{ .reg .u64 t; cvta.to.shared.u64 t, %1; cvt.u32.u64 %0, t; }" : "=r"(a) : "l"(p));
    return a;
}
#define CP_ASYNC(dst, src) \
    asm volatile("cp.async.cg.shared.global [%0], [%1], 16;" \
        :: "r"(dst), "l"(src) : "memory")
#define CP_COMMIT() asm volatile("cp.async.commit_group;" ::: "memory")
#define CP_WAIT(n)  asm volatile("cp.async.wait_group %0;" :: "n"(n) : "memory")

__device__ __forceinline__ void mma_bf16(float* c, const uint32_t* a, const uint32_t* b) {
    asm volatile(
        "mma.sync.aligned.m16n8k16.row.col.f32.bf16.bf16.f32 "
        "{%0,%1,%2,%3}, {%4,%5,%6,%7}, {%8,%9}, {%0,%1,%2,%3};"
        : "+f"(c[0]), "+f"(c[1]), "+f"(c[2]), "+f"(c[3])
        : "r"(a[0]), "r"(a[1]), "r"(a[2]), "r"(a[3]), "r"(b[0]), "r"(b[1]));
}
__device__ __forceinline__ void mma_f16(float* c, const uint32_t* a, const uint32_t* b) {
    asm volatile(
        "mma.sync.aligned.m16n8k16.row.col.f32.f16.f16.f32 "
        "{%0,%1,%2,%3}, {%4,%5,%6,%7}, {%8,%9}, {%0,%1,%2,%3};"
        : "+f"(c[0]), "+f"(c[1]), "+f"(c[2]), "+f"(c[3])
        : "r"(a[0]), "r"(a[1]), "r"(a[2]), "r"(a[3]), "r"(b[0]), "r"(b[1]));
}
__device__ __forceinline__ void ldsm_x4(uint32_t* r, uint32_t addr) {
    asm volatile("ldmatrix.sync.aligned.m8n8.x4.shared.b16 {%0,%1,%2,%3}, [%4];"
        : "=r"(r[0]), "=r"(r[1]), "=r"(r[2]), "=r"(r[3]) : "r"(addr));
}

// ---------------- tile geometry (2-byte elems, BK=64, 128B data + 16B pad rows) ----
#define ROW_BYTES 144
#define TILE_BYTES (128 * ROW_BYTES)             // 18432
#define STAGE_BYTES (2 * TILE_BYTES)
#define GEMM_SMEM (2 * STAGE_BYTES)              // 73728

// ---------------- 16-bit mma.sync GEMM: C = A[M,K] @ B[N,K]^T (+bias) ----------------
// BF: 0 = fp16 mma, 1 = bf16 mma.  MODE: 0 = fp32 out, 1 = fp16 out.
// Requires M%128==0, N%128==0, K%64==0.
template <int BF, int MODE>
__global__ __launch_bounds__(256, 2) void gemm_h(
    const __half* __restrict__ Ab, const __half* __restrict__ Bb,
    const float* __restrict__ bias, float* __restrict__ Cfb,
    __half* __restrict__ Chb,
    int N, int K, int lda, int ldb, int ldc,
    long long aBatch, long long bBatch, long long cBatch)
{
    extern __shared__ char smem[];
    const uint32_t su = smem_u32(smem);

    const int tid = threadIdx.x;
    const int warp = tid >> 5;
    const int lane = tid & 31;
    const int wm = warp & 1;
    const int wn = warp >> 1;
    const __half* A = Ab + (long long)blockIdx.z * aBatch;
    const __half* B = Bb + (long long)blockIdx.z * bBatch;
    float* Cf = Cfb + (long long)blockIdx.z * cBatch;
    __half* Ch = Chb + (long long)blockIdx.z * cBatch;
    const int bm0 = blockIdx.y * 128;
    const int bn0 = blockIdx.x * 128;

    int smoff[4];
    const __half* aptr[4];
    const __half* bptr[4];
#pragma unroll
    for (int i = 0; i < 4; i++) {
        int idx = tid + i * 256;
        int r = idx >> 3;
        int c4 = idx & 7;                  // 8 x 16B = 64 halves per row
        smoff[i] = r * ROW_BYTES + c4 * 16;
        aptr[i] = A + (size_t)(bm0 + r) * lda + c4 * 8;
        bptr[i] = B + (size_t)(bn0 + r) * ldb + c4 * 8;
    }

    const int a_off = (wm * 64 + ((lane >> 3) & 1) * 8 + (lane & 7)) * ROW_BYTES
                      + (lane >> 4) * 16;
    const int b_off = (wn * 32 + ((lane >> 4) << 3) + (lane & 7)) * ROW_BYTES
                      + (((lane >> 3) & 1)) * 16;

    float acc[4][4][4];
#pragma unroll
    for (int mt = 0; mt < 4; mt++)
#pragma unroll
        for (int nt = 0; nt < 4; nt++)
#pragma unroll
            for (int j = 0; j < 4; j++) acc[mt][nt][j] = 0.f;

    const int nsteps = K >> 6;             // BK = 64
    {
        uint32_t sb = su;
#pragma unroll
        for (int i = 0; i < 4; i++) CP_ASYNC(sb + smoff[i], aptr[i]);
#pragma unroll
        for (int i = 0; i < 4; i++) CP_ASYNC(sb + TILE_BYTES + smoff[i], bptr[i]);
        CP_COMMIT();
    }

    for (int s = 0; s < nsteps; s++) {
        CP_WAIT(0);
        __syncthreads();
        if (s + 1 < nsteps) {
            uint32_t sb = su + ((s + 1) & 1) * STAGE_BYTES;
            const int k0 = (s + 1) << 6;
#pragma unroll
            for (int i = 0; i < 4; i++) CP_ASYNC(sb + smoff[i], aptr[i] + k0);
#pragma unroll
            for (int i = 0; i < 4; i++) CP_ASYNC(sb + TILE_BYTES + smoff[i], bptr[i] + k0);
            CP_COMMIT();
        }

        const uint32_t sa = su + (s & 1) * STAGE_BYTES + a_off;
        const uint32_t sbb = su + (s & 1) * STAGE_BYTES + TILE_BYTES + b_off;

#pragma unroll
        for (int kk = 0; kk < 4; kk++) {   // 4 x k16 = 64
            uint32_t a_regs[4][4], b_regs[2][4];
#pragma unroll
            for (int mt = 0; mt < 4; mt++)
                ldsm_x4(a_regs[mt], sa + mt * 16 * ROW_BYTES + kk * 32);
#pragma unroll
            for (int pr = 0; pr < 2; pr++)
                ldsm_x4(b_regs[pr], sbb + pr * 16 * ROW_BYTES + kk * 32);
#pragma unroll
            for (int mt = 0; mt < 4; mt++)
#pragma unroll
                for (int nt = 0; nt < 4; nt++) {
                    if (BF) mma_bf16(acc[mt][nt], a_regs[mt], &b_regs[nt >> 1][(nt & 1) * 2]);
                    else    mma_f16(acc[mt][nt], a_regs[mt], &b_regs[nt >> 1][(nt & 1) * 2]);
                }
        }
    }

    const bool has_bias = (bias != nullptr);
    const int gr = lane >> 2;
    const int gc = lane & 3;
#pragma unroll
    for (int mt = 0; mt < 4; mt++) {
        int r0 = bm0 + wm * 64 + mt * 16 + gr;
#pragma unroll
        for (int nt = 0; nt < 4; nt++) {
            int c0 = bn0 + wn * 32 + nt * 8 + gc * 2;
            float bx = has_bias ? bias[c0] : 0.f;
            float by = has_bias ? bias[c0 + 1] : 0.f;
            float v00 = acc[mt][nt][0] + bx, v01 = acc[mt][nt][1] + by;
            float v10 = acc[mt][nt][2] + bx, v11 = acc[mt][nt][3] + by;
            if (MODE == 0) {
                *(float2*)&Cf[(size_t)r0 * ldc + c0] = make_float2(v00, v01);
                *(float2*)&Cf[(size_t)(r0 + 8) * ldc + c0] = make_float2(v10, v11);
            } else {
                *(__half2*)&Ch[(size_t)r0 * ldc + c0] = __floats2half2_rn(v00, v01);
                *(__half2*)&Ch[(size_t)(r0 + 8) * ldc + c0] = __floats2half2_rn(v10, v11);
            }
        }
    }
}

// ---------------- one-shot fp16 conversion + merging of external operands ----------------
__device__ __forceinline__ void h_seg(const float* s, __half* d, int n,
                                      int gid, int gsz) {
    for (int i = gid; i < n; i += gsz) d[i] = __float2half_rn(s[i]);
}
__global__ __launch_bounds__(256) void round_all(
    const float* x, __half* xh,
    const float* wqd, const float* wkvd, __half* wdh,
    const float* wqu, __half* wquh,
    const float* wku, const float* wvu, __half* wuvh,
    const float* wo, __half* woh,
    const float* bqd, const float* bkvd, float* bdm,
    const float* bku, const float* bvu, float* buvm)
{
    int gid = blockIdx.x * blockDim.x + threadIdx.x;
    int gsz = gridDim.x * blockDim.x;
    h_seg(x, xh, S_LEN * D_MODEL, gid, gsz);
    h_seg(wqd, wdh, CQ_DIM * D_MODEL, gid, gsz);                       // rows 0..96
    h_seg(wkvd, wdh + 128 * D_MODEL, CKV_DIM * D_MODEL, gid, gsz);     // rows 128..640
    for (int i = gid; i < 32 * D_MODEL; i += gsz)                      // zero gap rows
        wdh[96 * D_MODEL + i] = __float2half_rn(0.f);
    for (int i = gid; i < NH * HDIM * CQ_DIM; i += gsz) {              // wqu -> ldb 128 (pad cols zero-init)
        int r = i / CQ_DIM, c = i % CQ_DIM;
        wquh[r * 128 + c] = __float2half_rn(wqu[i]);
    }
    h_seg(wku, wuvh, NH * HDIM * CKV_DIM, gid, gsz);
    h_seg(wvu, wuvh + NH * HDIM * CKV_DIM, NH * HDIM * CKV_DIM, gid, gsz);
    h_seg(wo, woh, D_MODEL * NH * HDIM, gid, gsz);
    for (int i = gid; i < NDOWNP; i += gsz)
        bdm[i] = (i < CQ_DIM) ? bqd[i] : ((i < 128) ? 0.f : bkvd[i - 128]);
    for (int i = gid; i < NUV; i += gsz)
        buvm[i] = (i < 2048) ? bku[i] : bvu[i - 2048];
}

// ---------------- RoPE + bf16 hi/lo pack (K=384 concat) ----------------
__global__ __launch_bounds__(256) void rope_pack(
    const float* __restrict__ q, const float* __restrict__ kv,
    const float* __restrict__ cosb, const float* __restrict__ sinb,
    __nv_bfloat16* __restrict__ qc, __nv_bfloat16* __restrict__ kc)
{
    int idx = blockIdx.x * blockDim.x + threadIdx.x;
    int dh = idx & 63;
    int t = idx >> 6;
    int h = t & (NH - 1);
    int s = t >> 4;
    if (s >= S_LEN) return;

    float c1 = cosb[s * HDIM + dh];
    float s1 = sinb[s * HDIM + dh];
    float c2 = cosb[s * HDIM + dh + 64];
    float s2 = sinb[s * HDIM + dh + 64];

    size_t qbase = (size_t)s * (NH * HDIM) + h * HDIM + dh;
    size_t kbase = (size_t)s * NUV + h * HDIM + dh;
    const float sc = 0.08838834764831845f;  // 1/sqrt(128)

    float q1 = q[qbase], q2 = q[qbase + 64];
    float qa = (q1 * c1 - q2 * s1) * sc;
    float qb = (q2 * c2 + q1 * s2) * sc;
    float k1 = kv[kbase], k2 = kv[kbase + 64];
    float ka = k1 * c1 - k2 * s1;
    float kb = k2 * c2 + k1 * s2;

    __nv_bfloat16 qah = __float2bfloat16_rn(qa);
    __nv_bfloat16 qal = __float2bfloat16_rn(qa - __bfloat162float(qah));
    __nv_bfloat16 qbh = __float2bfloat16_rn(qb);
    __nv_bfloat16 qbl = __float2bfloat16_rn(qb - __bfloat162float(qbh));
    __nv_bfloat16 kah = __float2bfloat16_rn(ka);
    __nv_bfloat16 kal = __float2bfloat16_rn(ka - __bfloat162float(kah));
    __nv_bfloat16 kbh = __float2bfloat16_rn(kb);
    __nv_bfloat16 kbl = __float2bfloat16_rn(kb - __bfloat162float(kbh));

    size_t ob = ((size_t)h * S_LEN + s) * 384 + dh;
    qc[ob]       = qah; qc[ob + 64]       = qbh;
    qc[ob + 128] = qah; qc[ob + 128 + 64] = qbh;
    qc[ob + 256] = qal; qc[ob + 256 + 64] = qbl;
    kc[ob]       = kah; kc[ob + 64]       = kbh;
    kc[ob + 128] = kal; kc[ob + 128 + 64] = kbl;
    kc[ob + 256] = kah; kc[ob + 256 + 64] = kbh;
}

// ---------------- row softmax over 2048-wide rows -> fp16 out ----------------
__global__ __launch_bounds__(256) void softmax_rows(
    const float* __restrict__ L, __half* __restrict__ P)
{
    __shared__ float red[8];
    const float* p = L + (size_t)blockIdx.x * 2048;
    __half* po = P + (size_t)blockIdx.x * 2048;
    const int tid = threadIdx.x;
    const int wid = tid >> 5;
    const int lid = tid & 31;

    float4 a = ((const float4*)p)[tid];
    float4 b = ((const float4*)p)[tid + 256];

    float mx = fmaxf(fmaxf(fmaxf(a.x, a.y), fmaxf(a.z, a.w)),
                     fmaxf(fmaxf(b.x, b.y), fmaxf(b.z, b.w)));
#pragma unroll
    for (int m = 16; m > 0; m >>= 1) mx = fmaxf(mx, __shfl_xor_sync(~0u, mx, m));
    if (lid == 0) red[wid] = mx;
    __syncthreads();
    if (wid == 0) {
        float v = red[lid & 7];
#pragma unroll
        for (int m = 4; m > 0; m >>= 1) v = fmaxf(v, __shfl_xor_sync(~0u, v, m));
        if (lid == 0) red[0] = v;
    }
    __syncthreads();
    mx = red[0];
    __syncthreads();

    a.x = __expf(a.x - mx); a.y = __expf(a.y - mx); a.z = __expf(a.z - mx); a.w = __expf(a.w - mx);
    b.x = __expf(b.x - mx); b.y = __expf(b.y - mx); b.z = __expf(b.z - mx); b.w = __expf(b.w - mx);
    float sm = a.x + a.y + a.z + a.w + b.x + b.y + b.z + b.w;
#pragma unroll
    for (int m = 16; m > 0; m >>= 1) sm += __shfl_xor_sync(~0u, sm, m);
    if (lid == 0) red[wid] = sm;
    __syncthreads();
    if (wid == 0) {
        float v = red[lid & 7];
#pragma unroll
        for (int m = 4; m > 0; m >>= 1) v += __shfl_xor_sync(~0u, v, m);
        if (lid == 0) red[0] = v;
    }
    __syncthreads();
    const float inv = 1.f / red[0];

    ((__half2*)po)[tid * 2]       = __floats2half2_rn(a.x * inv, a.y * inv);
    ((__half2*)po)[tid * 2 + 1]   = __floats2half2_rn(a.z * inv, a.w * inv);
    ((__half2*)po)[512 + tid * 2] = __floats2half2_rn(b.x * inv, b.y * inv);
    ((__half2*)po)[513 + tid * 2] = __floats2half2_rn(b.z * inv, b.w * inv);
}

// ---------------- transpose v (fp32, ld 4096) -> vt fp16 [h][d][s] ----------------
__global__ void transpose_v(const float* __restrict__ src, __half* __restrict__ dst)
{
    __shared__ float t[32][33];
    int x = threadIdx.x, y = threadIdx.y;
    int r0 = blockIdx.y * 32, c0 = blockIdx.x * 32;
#pragma unroll
    for (int i = 0; i < 32; i += 8)
        t[y + i][x] = src[(size_t)(r0 + y + i) * NUV + c0 + x];
    __syncthreads();
#pragma unroll
    for (int i = 0; i < 32; i += 8)
        dst[(size_t)(c0 + y + i) * 2048 + r0 + x] = __float2half_rn(t[x][y + i]);
}

// ---------------- launch ----------------
extern "C" void kernel_launch(void* const* d_in, const int* in_sizes, int n_in,
                              void* d_out, int out_size)
{
    const float* x        = (const float*)d_in[0];
    const float* rope_cos = (const float*)d_in[1];
    const float* rope_sin = (const float*)d_in[2];
    const float* wq_down  = (const float*)d_in[3];
    const float* bq_down  = (const float*)d_in[4];
    const float* wq_up    = (const float*)d_in[5];
    const float* bq_up    = (const float*)d_in[6];
    const float* wkv_down = (const float*)d_in[7];
    const float* bkv_down = (const float*)d_in[8];
    const float* wk_up    = (const float*)d_in[9];
    const float* bk_up    = (const float*)d_in[10];
    const float* wv_up    = (const float*)d_in[11];
    const float* bv_up    = (const float*)d_in[12];
    const float* wo       = (const float*)d_in[13];
    const float* bo       = (const float*)d_in[14];
    float* out = (float*)d_out;

    __half *xh, *wdh, *wquh, *wuvh, *woh, *cqkvh, *Ph, *vth, *attnh;
    float *bdm, *buvm, *q, *kv, *logits;
    __nv_bfloat16 *qcb, *kcb;
    cudaGetSymbolAddress((void**)&xh,     g_xh);
    cudaGetSymbolAddress((void**)&wdh,    g_wdh);
    cudaGetSymbolAddress((void**)&wquh,   g_wquh);
    cudaGetSymbolAddress((void**)&wuvh,   g_wuvh);
    cudaGetSymbolAddress((void**)&woh,    g_woh);
    cudaGetSymbolAddress((void**)&cqkvh,  g_cqkvh);
    cudaGetSymbolAddress((void**)&Ph,     g_Ph);
    cudaGetSymbolAddress((void**)&vth,    g_vth);
    cudaGetSymbolAddress((void**)&attnh,  g_attnh);
    cudaGetSymbolAddress((void**)&bdm,    g_bdm);
    cudaGetSymbolAddress((void**)&buvm,   g_buvm);
    cudaGetSymbolAddress((void**)&q,      g_q);
    cudaGetSymbolAddress((void**)&kv,     g_kv);
    cudaGetSymbolAddress((void**)&logits, g_logits);
    cudaGetSymbolAddress((void**)&qcb,    g_qcb);
    cudaGetSymbolAddress((void**)&kcb,    g_kcb);

    cudaFuncSetAttribute(gemm_h<0,0>, cudaFuncAttributeMaxDynamicSharedMemorySize, GEMM_SMEM);
    cudaFuncSetAttribute(gemm_h<0,1>, cudaFuncAttributeMaxDynamicSharedMemorySize, GEMM_SMEM);
    cudaFuncSetAttribute(gemm_h<1,0>, cudaFuncAttributeMaxDynamicSharedMemorySize, GEMM_SMEM);

    const long long SS = (long long)S_LEN * S_LEN;
    const long long S384 = (long long)S_LEN * 384;

    // 0: convert + merge external operands to fp16
    round_all<<<512, 256>>>(x, xh, wq_down, wkv_down, wdh, wq_up, wquh,
                            wk_up, wv_up, wuvh, wo, woh,
                            bq_down, bkv_down, bdm, bk_up, bv_up, buvm);

    // 1: [c_q|pad|c_kv] = x @ wdh^T + bdm    [2048, 640] fp16 out
    gemm_h<0,1><<<dim3(5, 16, 1), 256, GEMM_SMEM>>>(
        xh, wdh, bdm, nullptr, cqkvh, NDOWNP, D_MODEL, D_MODEL, D_MODEL, NDOWNP, 0, 0, 0);
    // 2: q = c_q @ wqu^T + b                 [2048, 2048] fp32 out (K=128 padded)
    gemm_h<0,0><<<dim3(16, 16, 1), 256, GEMM_SMEM>>>(
        cqkvh, wquh, bq_up, q, nullptr, 2048, 128, NDOWNP, 128, 2048, 0, 0, 0);
    // 3: [k|v] = c_kv @ wuv^T + b            [2048, 4096] fp32 out
    gemm_h<0,0><<<dim3(32, 16, 1), 256, GEMM_SMEM>>>(
        cqkvh + 128, wuvh, buvm, kv, nullptr, NUV, CKV_DIM, NDOWNP, CKV_DIM, NUV, 0, 0, 0);

    // 4: rope + bf16 hi/lo pack
    rope_pack<<<(S_LEN * NH * 64) / 256, 256>>>(q, kv, rope_cos, rope_sin, qcb, kcb);

    // 5: logits[h] = Q'_h @ K'_h^T  (bf16 3-term concat, K=384)   <- ncu slot
    gemm_h<1,0><<<dim3(16, 16, NH), 256, GEMM_SMEM>>>(
        (const __half*)qcb, (const __half*)kcb, nullptr, logits, nullptr,
        2048, 384, 384, 384, 2048, S384, S384, SS);

    // 6: softmax rows -> fp16 P
    softmax_rows<<<NH * S_LEN, 256>>>(logits, Ph);

    // 7: v^T -> fp16 vt [h][d][s]
    transpose_v<<<dim3(64, 64), dim3(32, 8)>>>(kv + 2048, vth);

    // 8: attn[h] = P_h @ Vt_h^T   M=2048, N=128, K=2048, fp16 out
    gemm_h<0,1><<<dim3(1, 16, NH), 256, GEMM_SMEM>>>(
        Ph, vth, nullptr, nullptr, attnh, HDIM, 2048, 2048, 2048, 2048,
        SS, (long long)HDIM * 2048, HDIM);

    // 9: out = attn @ wo^T + bo              [2048, 2048] fp32 out
    gemm_h<0,0><<<dim3(16, 16, 1), 256, GEMM_SMEM>>>(
        attnh, woh, bo, out, nullptr, 2048, 2048, 2048, 2048, 2048, 0, 0, 0);
}